// round 14
// baseline (speedup 1.0000x reference)
#include <cuda_runtime.h>
#include <cuda_bf16.h>
#include <math.h>
#include <stdint.h>

#define BB 2
#define NN 8192
#define DIMM 512
#define GH 6
#define DH 64
#define NBF 256
#define NWIN 32
#define WINSZ 256
#define BHG (BB*GH)      // 12
#define BHL 4            // B * LOCAL_HEADS
#define NSPLIT 32

// ---------------- scratch (device globals: alloc-free) ----------------
__device__ float g_q[BB*NN*DIMM];
__device__ float g_k[BB*NN*DIMM];
__device__ float g_v[BB*NN*DIMM];
__device__ float g_qp[BHG*NN*NBF];
__device__ float g_kp[BHG*NN*NBF];      // raw k dd scores
__device__ float g_kdiag[BHG*NN];
__device__ float g_kmaxp[BHG*128];
__device__ float g_kmax[BHG];
__device__ float g_part[BHG*NSPLIT*256*65];
__device__ float g_ctx[BHG*256*68];
__device__ float g_dinv[BHG*NN];
__device__ float g_att[BB*NN*DIMM];
__device__ float g_sc[(size_t)BHL*NWIN*WINSZ*768];
__device__ float g_rq[BHL*NN*DH];
__device__ float g_rk[BHL*NN*DH];
__device__ float g_rowm[BHL*NWIN*WINSZ];
__device__ float g_rows[BHL*NWIN*WINSZ];
__device__ float g_w[4*512*512];                 // transposed weights fp32 (Q,K,V,O)
__device__ __nv_bfloat16 g_wh[4*512*512];        // bf16 hi
__device__ __nv_bfloat16 g_wl[4*512*512];        // bf16 lo
__device__ __nv_bfloat16 g_xh[BB*NN*DIMM];
__device__ __nv_bfloat16 g_xl[BB*NN*DIMM];
__device__ __nv_bfloat16 g_ath[BB*NN*DIMM];
__device__ __nv_bfloat16 g_atl[BB*NN*DIMM];

// ================= bf16 hi/lo split helpers =================
__device__ __forceinline__ void cvt_hl(float f0, float f1, uint32_t& hi, uint32_t& lo) {
    __nv_bfloat16 h0 = __float2bfloat16_rn(f0), h1 = __float2bfloat16_rn(f1);
    float r0 = f0 - __bfloat162float(h0), r1 = f1 - __bfloat162float(h1);
    __nv_bfloat162 hh; hh.x = h0; hh.y = h1;
    __nv_bfloat162 ll = __floats2bfloat162_rn(r0, r1);
    hi = *reinterpret_cast<uint32_t*>(&hh);
    lo = *reinterpret_cast<uint32_t*>(&ll);
}
__device__ __forceinline__ void mma_bf16(float* c, const uint32_t* a, const uint32_t* b) {
    asm volatile(
        "mma.sync.aligned.m16n8k16.row.col.f32.bf16.bf16.f32 "
        "{%0,%1,%2,%3}, {%4,%5,%6,%7}, {%8,%9}, {%0,%1,%2,%3};"
        : "+f"(c[0]), "+f"(c[1]), "+f"(c[2]), "+f"(c[3])
        : "r"(a[0]), "r"(a[1]), "r"(a[2]), "r"(a[3]), "r"(b[0]), "r"(b[1]));
}
__device__ __forceinline__ uint32_t cvta_smem(const void* p) {
    uint32_t a;
    asm("{ .reg .u64 t; cvta.to.shared.u64 t, %1; cvt.u32.u64 %0, t; }" : "=r"(a) : "l"(p));
    return a;
}
__device__ __forceinline__ void ldsm_x4(uint32_t addr, uint32_t* d) {
    asm volatile("ldmatrix.sync.aligned.m8n8.x4.shared.b16 {%0,%1,%2,%3}, [%4];"
        : "=r"(d[0]), "=r"(d[1]), "=r"(d[2]), "=r"(d[3]) : "r"(addr));
}
__device__ __forceinline__ void cp16(uint32_t s, const void* g) {
    asm volatile("cp.async.cg.shared.global [%0], [%1], 16;" :: "r"(s), "l"(g));
}
#define CP_COMMIT() asm volatile("cp.async.commit_group;" ::: "memory")
#define CP_WAIT1()  asm volatile("cp.async.wait_group 1;" ::: "memory")
#define CP_WAIT0()  asm volatile("cp.async.wait_group 0;" ::: "memory")

// ================= weight transpose (all 4 in one launch) =================
__global__ void wtrans4(const float* __restrict__ W0, const float* __restrict__ W1,
                        const float* __restrict__ W2, const float* __restrict__ W3,
                        float* __restrict__ wout)
{
    __shared__ float t[32][33];
    const float* W = (blockIdx.z == 0) ? W0 : (blockIdx.z == 1) ? W1 : (blockIdx.z == 2) ? W2 : W3;
    float* out = wout + (size_t)blockIdx.z * 512 * 512;
    int n0 = blockIdx.x * 32, k0 = blockIdx.y * 32;
    int tx = threadIdx.x, ty = threadIdx.y;
#pragma unroll
    for (int i = ty; i < 32; i += 8) t[i][tx] = W[(size_t)(k0 + i) * 512 + n0 + tx];
    __syncthreads();
#pragma unroll
    for (int i = ty; i < 32; i += 8) out[(size_t)(n0 + i) * 512 + k0 + tx] = t[tx][i];
}

// ================= fp32 -> bf16 hi/lo conversion (8 elems/thread) =================
__global__ void conv_hl(const float* __restrict__ in, __nv_bfloat16* __restrict__ oh,
                        __nv_bfloat16* __restrict__ ol)
{
    size_t i = ((size_t)blockIdx.x * 256 + threadIdx.x) * 8;
    float4 a = *(const float4*)(in + i), b = *(const float4*)(in + i + 4);
    float v[8] = {a.x, a.y, a.z, a.w, b.x, b.y, b.z, b.w};
    uint32_t h[4], l[4];
#pragma unroll
    for (int j = 0; j < 4; j++) cvt_hl(v[2*j], v[2*j+1], h[j], l[j]);
    *(uint4*)(oh + i) = make_uint4(h[0], h[1], h[2], h[3]);
    *(uint4*)(ol + i) = make_uint4(l[0], l[1], l[2], l[3]);
}

// ================= bf16x3 GEMM 128x128: cp.async 2-stage + ldmatrix + mma =================
#define STW 20
#define STAGE_W 10240     // Ah 2560 | Al 2560 | Bh 2560 | Bl 2560
#define GSMEM_BYTES (2*STAGE_W*4)

__global__ void __launch_bounds__(256, 2) gemm_bfq(
    const __nv_bfloat16* __restrict__ Ah, const __nv_bfloat16* __restrict__ Al,
    const __nv_bfloat16* __restrict__ Bh, const __nv_bfloat16* __restrict__ Bl,
    const float* __restrict__ bias,
    float* __restrict__ o0, float* __restrict__ o1, float* __restrict__ o2)
{
    extern __shared__ uint32_t smw[];
    const int K = 512;
    const int NC = 16;
    int tid = threadIdx.x;
    int wid = tid >> 5, lane = tid & 31;
    int wm = wid >> 1, wn = wid & 1;           // 4(m) x 2(n); warp tile 32 x 64
    int m0 = blockIdx.y * 128, n0 = blockIdx.x * 128;
    int r = lane >> 2, cq = lane & 3;
    int lr = lane & 7, lg = lane >> 3;
    float acc[2][8][4];
#pragma unroll
    for (int i = 0; i < 2; i++)
#pragma unroll
        for (int j = 0; j < 8; j++)
#pragma unroll
            for (int t = 0; t < 4; t++) acc[i][j][t] = 0.f;
    uint32_t smbase = cvta_smem(smw);
    uint32_t aoff = (uint32_t)(((wm * 32 + (lg & 1) * 8 + lr) * STW + (lg >> 1) * 4) * 4);
    uint32_t boff = (uint32_t)(((wn * 64 + (lg >> 1) * 8 + lr) * STW + (lg & 1) * 4) * 4);

    int arow = tid >> 1, acz = (tid & 1) * 16;
    const __nv_bfloat16* agh = Ah + (size_t)(m0 + arow) * K + acz;
    const __nv_bfloat16* agl = Al + (size_t)(m0 + arow) * K + acz;
    const __nv_bfloat16* bgh = Bh + (size_t)(n0 + arow) * K + acz;
    const __nv_bfloat16* bgl = Bl + (size_t)(n0 + arow) * K + acz;
    uint32_t s_off = (uint32_t)((arow * STW + (tid & 1) * 8) * 4);

#define PREFETCH(s, k0) do { \
    uint32_t st = smbase + (uint32_t)(s) * (STAGE_W * 4); \
    cp16(st + s_off,                  agh + (k0)); \
    cp16(st + s_off + 16,             agh + (k0) + 8); \
    cp16(st + 2560 * 4 + s_off,       agl + (k0)); \
    cp16(st + 2560 * 4 + s_off + 16,  agl + (k0) + 8); \
    cp16(st + 5120 * 4 + s_off,       bgh + (k0)); \
    cp16(st + 5120 * 4 + s_off + 16,  bgh + (k0) + 8); \
    cp16(st + 7680 * 4 + s_off,       bgl + (k0)); \
    cp16(st + 7680 * 4 + s_off + 16,  bgl + (k0) + 8); \
    CP_COMMIT(); \
} while (0)

#define DO_MMA(s) do { \
    uint32_t sb0 = smbase + (uint32_t)(s) * (STAGE_W * 4); \
    _Pragma("unroll") \
    for (int ks = 0; ks < 2; ks++) { \
        uint32_t kb = (uint32_t)(ks * 32); \
        uint32_t ah[2][4], al[2][4], bq[4][4], bl[4][4]; \
        _Pragma("unroll") \
        for (int mt = 0; mt < 2; mt++) { \
            ldsm_x4(sb0 + aoff + mt * (16 * STW * 4) + kb, ah[mt]); \
            ldsm_x4(sb0 + 2560 * 4 + aoff + mt * (16 * STW * 4) + kb, al[mt]); \
        } \
        _Pragma("unroll") \
        for (int p = 0; p < 4; p++) { \
            ldsm_x4(sb0 + 5120 * 4 + boff + p * (16 * STW * 4) + kb, bq[p]); \
            ldsm_x4(sb0 + 7680 * 4 + boff + p * (16 * STW * 4) + kb, bl[p]); \
        } \
        _Pragma("unroll") \
        for (int mt = 0; mt < 2; mt++) \
            _Pragma("unroll") \
            for (int nt = 0; nt < 8; nt++) { \
                const uint32_t* bh2 = &bq[nt >> 1][(nt & 1) * 2]; \
                const uint32_t* bl2 = &bl[nt >> 1][(nt & 1) * 2]; \
                mma_bf16(acc[mt][nt], ah[mt], bh2); \
                mma_bf16(acc[mt][nt], ah[mt], bl2); \
                mma_bf16(acc[mt][nt], al[mt], bh2); \
            } \
    } \
} while (0)

    PREFETCH(0, 0);
    for (int it = 0; it < NC; ++it) {
        if (it + 1 < NC) { PREFETCH((it + 1) & 1, (it + 1) * 32); CP_WAIT1(); }
        else             { CP_WAIT0(); }
        __syncthreads();
        DO_MMA(it & 1);
        __syncthreads();
    }

    int sel = n0 >> 9;
    int colb = n0 & 511;
    float* ob = (sel == 0) ? o0 : (sel == 1) ? o1 : o2;
#pragma unroll
    for (int mt = 0; mt < 2; mt++)
#pragma unroll
        for (int nt = 0; nt < 8; nt++) {
            int row = m0 + wm * 32 + mt * 16 + r;
            int col = colb + wn * 64 + nt * 8 + 2 * cq;
            float2 v0 = make_float2(acc[mt][nt][0], acc[mt][nt][1]);
            float2 v1 = make_float2(acc[mt][nt][2], acc[mt][nt][3]);
            if (bias) {
                float2 bv = *(const float2*)(bias + col);
                v0.x += bv.x; v0.y += bv.y;
                v1.x += bv.x; v1.y += bv.y;
            }
            *(float2*)(ob + (size_t)row * 512 + col) = v0;
            *(float2*)(ob + (size_t)(row + 8) * 512 + col) = v1;
        }
#undef PREFETCH
#undef DO_MMA
}

// ================= dd via bf16x3 mma: CTA = 64 rows x 256 features, K=64 =================
#define DSTW 12

#define DD_MAINLOOP() \
    float acc[2][8][4]; \
    _Pragma("unroll") \
    for (int i = 0; i < 2; i++) _Pragma("unroll") for (int j = 0; j < 8; j++) \
        _Pragma("unroll") for (int t = 0; t < 4; t++) acc[i][j][t] = 0.f; \
    int ar = tid >> 2, akq = (tid & 3) * 4; \
    const float* ab = data + ((size_t)b * NN + n0 + ar) * DIMM + h * 64 + akq; \
    const float* pbb = proj + (size_t)tid * 64; \
    float sumsq = 0.f; \
    for (int kc = 0; kc < 4; kc++) { \
        float4 va = *(const float4*)(ab + kc * 16); \
        float x0 = va.x * NORM, x1 = va.y * NORM, x2 = va.z * NORM, x3 = va.w * NORM; \
        sumsq += x0 * x0 + x1 * x1 + x2 * x2 + x3 * x3; \
        uint32_t ah0, al0, ah1, al1; \
        cvt_hl(x0, x1, ah0, al0); cvt_hl(x2, x3, ah1, al1); \
        float4 vb0 = *(const float4*)(pbb + kc * 16); \
        float4 vb1 = *(const float4*)(pbb + kc * 16 + 4); \
        float4 vb2 = *(const float4*)(pbb + kc * 16 + 8); \
        float4 vb3 = *(const float4*)(pbb + kc * 16 + 12); \
        float bvv[16] = {vb0.x,vb0.y,vb0.z,vb0.w, vb1.x,vb1.y,vb1.z,vb1.w, \
                         vb2.x,vb2.y,vb2.z,vb2.w, vb3.x,vb3.y,vb3.z,vb3.w}; \
        uint32_t bhv[8], blv[8]; \
        _Pragma("unroll") \
        for (int i = 0; i < 8; i++) cvt_hl(bvv[2*i], bvv[2*i+1], bhv[i], blv[i]); \
        __syncthreads(); \
        *(uint2*)(Ahs + ar * DSTW + (akq >> 1)) = make_uint2(ah0, ah1); \
        *(uint2*)(Als + ar * DSTW + (akq >> 1)) = make_uint2(al0, al1); \
        *(uint4*)(Bhs + tid * DSTW)     = make_uint4(bhv[0], bhv[1], bhv[2], bhv[3]); \
        *(uint4*)(Bhs + tid * DSTW + 4) = make_uint4(bhv[4], bhv[5], bhv[6], bhv[7]); \
        *(uint4*)(Bls + tid * DSTW)     = make_uint4(blv[0], blv[1], blv[2], blv[3]); \
        *(uint4*)(Bls + tid * DSTW + 4) = make_uint4(blv[4], blv[5], blv[6], blv[7]); \
        __syncthreads(); \
        uint32_t afh[2][4], afl[2][4]; \
        _Pragma("unroll") \
        for (int mt = 0; mt < 2; mt++) { \
            int mr = (wm * 32 + mt * 16 + r) * DSTW + cq; \
            afh[mt][0] = Ahs[mr];       afh[mt][1] = Ahs[mr + 8 * DSTW]; \
            afh[mt][2] = Ahs[mr + 4];   afh[mt][3] = Ahs[mr + 8 * DSTW + 4]; \
            afl[mt][0] = Als[mr];       afl[mt][1] = Als[mr + 8 * DSTW]; \
            afl[mt][2] = Als[mr + 4];   afl[mt][3] = Als[mr + 8 * DSTW + 4]; \
        } \
        _Pragma("unroll") \
        for (int nt = 0; nt < 8; nt++) { \
            int nr = (wn * 64 + nt * 8 + r) * DSTW + cq; \
            uint32_t bf[2] = {Bhs[nr], Bhs[nr + 4]}; \
            uint32_t bg[2] = {Bls[nr], Bls[nr + 4]}; \
            _Pragma("unroll") \
            for (int mt = 0; mt < 2; mt++) { \
                mma_bf16(acc[mt][nt], afh[mt], bf); \
                mma_bf16(acc[mt][nt], afh[mt], bg); \
                mma_bf16(acc[mt][nt], afl[mt], bf); \
            } \
        } \
    }

__global__ void __launch_bounds__(256, 2) ddq_mma(
    const float* __restrict__ data, const float* __restrict__ proj, float* __restrict__ qp)
{
    __shared__ uint32_t Ahs[64*DSTW], Als[64*DSTW], Bhs[256*DSTW], Bls[256*DSTW];
    __shared__ float ssq[64][4];
    __shared__ float wred[64][4];
    __shared__ float rowbase[64];
    int bh = blockIdx.y; int b = bh / GH, h = bh % GH;
    int n0 = blockIdx.x * 64;
    int tid = threadIdx.x;
    int wid = tid >> 5, lane = tid & 31;
    int wm = wid >> 2, wn = wid & 3;
    int r = lane >> 2, cq = lane & 3;
    const float NORM = 0.35355339059327373f;

    DD_MAINLOOP();

    ssq[ar][tid & 3] = sumsq;
    float mx[2][2];
#pragma unroll
    for (int mt = 0; mt < 2; mt++)
#pragma unroll
        for (int hf = 0; hf < 2; hf++) {
            float m = -1e30f;
#pragma unroll
            for (int nt = 0; nt < 8; nt++)
                m = fmaxf(m, fmaxf(acc[mt][nt][hf*2], acc[mt][nt][hf*2+1]));
            m = fmaxf(m, __shfl_xor_sync(0xffffffffu, m, 1));
            m = fmaxf(m, __shfl_xor_sync(0xffffffffu, m, 2));
            mx[mt][hf] = m;
        }
    if (cq == 0) {
#pragma unroll
        for (int mt = 0; mt < 2; mt++)
#pragma unroll
            for (int hf = 0; hf < 2; hf++)
                wred[wm * 32 + mt * 16 + hf * 8 + r][wn] = mx[mt][hf];
    }
    __syncthreads();
    if (tid < 64) {
        float mm = fmaxf(fmaxf(wred[tid][0], wred[tid][1]), fmaxf(wred[tid][2], wred[tid][3]));
        float dg = 0.5f * (ssq[tid][0] + ssq[tid][1] + ssq[tid][2] + ssq[tid][3]);
        rowbase[tid] = dg + mm;
    }
    __syncthreads();
#pragma unroll
    for (int mt = 0; mt < 2; mt++) {
        int row_a = wm * 32 + mt * 16 + r, row_b = row_a + 8;
        float ba = rowbase[row_a], bb2 = rowbase[row_b];
        float* oa = qp + ((size_t)bh * NN + n0 + row_a) * NBF;
        float* ob = qp + ((size_t)bh * NN + n0 + row_b) * NBF;
#pragma unroll
        for (int nt = 0; nt < 8; nt++) {
            int col = wn * 64 + nt * 8 + 2 * cq;
            float2 o1, o2;
            o1.x = 0.0625f * (expf(acc[mt][nt][0] - ba) + 1e-4f);
            o1.y = 0.0625f * (expf(acc[mt][nt][1] - ba) + 1e-4f);
            o2.x = 0.0625f * (expf(acc[mt][nt][2] - bb2) + 1e-4f);
            o2.y = 0.0625f * (expf(acc[mt][nt][3] - bb2) + 1e-4f);
            *(float2*)(oa + col) = o1;
            *(float2*)(ob + col) = o2;
        }
    }
}

__global__ void __launch_bounds__(256, 2) ddk_mma(
    const float* __restrict__ data, const float* __restrict__ proj,
    float* __restrict__ kdd, float* __restrict__ kdiag, float* __restrict__ kmaxp)
{
    __shared__ uint32_t Ahs[64*DSTW], Als[64*DSTW], Bhs[256*DSTW], Bls[256*DSTW];
    __shared__ float ssq[64][4];
    __shared__ float red[8];
    int bh = blockIdx.y; int b = bh / GH, h = bh % GH;
    int n0 = blockIdx.x * 64;
    int tid = threadIdx.x;
    int wid = tid >> 5, lane = tid & 31;
    int wm = wid >> 2, wn = wid & 3;
    int r = lane >> 2, cq = lane & 3;
    const float NORM = 0.35355339059327373f;

    DD_MAINLOOP();

    ssq[ar][tid & 3] = sumsq;
    __syncthreads();
    if (tid < 64)
        kdiag[(size_t)bh * NN + n0 + tid] =
            0.5f * (ssq[tid][0] + ssq[tid][1] + ssq[tid][2] + ssq[tid][3]);
    float tmax = -1e30f;
#pragma unroll
    for (int mt = 0; mt < 2; mt++) {
        int row_a = wm * 32 + mt * 16 + r, row_b = row_a + 8;
        float* oa = kdd + ((size_t)bh * NN + n0 + row_a) * NBF;
        float* ob = kdd + ((size_t)bh * NN + n0 + row_b) * NBF;
#pragma unroll
        for (int nt = 0; nt < 8; nt++) {
            int col = wn * 64 + nt * 8 + 2 * cq;
            float2 o1 = make_float2(acc[mt][nt][0], acc[mt][nt][1]);
            float2 o2 = make_float2(acc[mt][nt][2], acc[mt][nt][3]);
            tmax = fmaxf(tmax, fmaxf(fmaxf(o1.x, o1.y), fmaxf(o2.x, o2.y)));
            *(float2*)(oa + col) = o1;
            *(float2*)(ob + col) = o2;
        }
    }
#pragma unroll
    for (int o = 16; o > 0; o >>= 1) tmax = fmaxf(tmax, __shfl_xor_sync(0xffffffffu, tmax, o));
    if (lane == 0) red[wid] = tmax;
    __syncthreads();
    if (tid == 0) {
        float z = red[0];
#pragma unroll
        for (int i = 1; i < 8; i++) z = fmaxf(z, red[i]);
        kmaxp[bh * 128 + blockIdx.x] = z;
    }
}

__global__ void kmax_final_kernel(const float* __restrict__ kpart, float* __restrict__ kmax)
{
    int bh = blockIdx.x;
    float m = kpart[bh * 128 + threadIdx.x];
#pragma unroll
    for (int o = 16; o > 0; o >>= 1) m = fmaxf(m, __shfl_xor_sync(0xffffffffu, m, o));
    __shared__ float red[4];
    if ((threadIdx.x & 31) == 0) red[threadIdx.x >> 5] = m;
    __syncthreads();
    if (threadIdx.x == 0)
        kmax[bh] = fmaxf(fmaxf(red[0], red[1]), fmaxf(red[2], red[3]));
}

// ---------------- ctx: exp applied inline on raw kdd ----------------
__global__ void __launch_bounds__(256) ctx_partial_kernel(
    const float* __restrict__ kdd, const float* __restrict__ kdiag,
    const float* __restrict__ kmax, const float* __restrict__ v, float* __restrict__ part)
{
    int bh = blockIdx.x, sp = blockIdx.y;
    int b = bh / GH, h = bh % GH;
    int j = threadIdx.x;
    float acc[65];
#pragma unroll
    for (int d = 0; d < 65; d++) acc[d] = 0.f;
    __shared__ __align__(16) float vs[16][68];
    float km = kmax[bh];
    const float* kpb = kdd + ((size_t)bh * NN + sp * 256) * NBF + j;
    const float* dgb = kdiag + (size_t)bh * NN + sp * 256;
    const float* vb = v + ((size_t)b * NN + sp * 256) * DIMM + h * 64;
    for (int n0 = 0; n0 < 256; n0 += 16) {
        __syncthreads();
        int r = threadIdx.x >> 4;
        int c = (threadIdx.x & 15) * 4;
        float4 vv = *(const float4*)(vb + (size_t)(n0 + r) * DIMM + c);
        *(float4*)&vs[r][c] = vv;
        if ((threadIdx.x & 15) == 0) vs[r][64] = 1.f;
        if ((threadIdx.x & 15) == 1) vs[r][65] = dgb[n0 + r];
        __syncthreads();
#pragma unroll 2
        for (int nn = 0; nn < 16; nn++) {
            float praw = kpb[(size_t)(n0 + nn) * NBF];
            float p = 0.0625f * (expf(praw - vs[nn][65] - km) + 1e-4f);
#pragma unroll
            for (int d = 0; d < 65; d++) acc[d] += p * vs[nn][d];
        }
    }
    float* o = part + (((size_t)bh * NSPLIT + sp) * 256 + j) * 65;
#pragma unroll
    for (int d = 0; d < 65; d++) o[d] = acc[d];
}
__global__ void ctx_reduce_kernel(const float* __restrict__ part, float* __restrict__ ctx)
{
    int idx = blockIdx.x * 256 + threadIdx.x;
    if (idx >= BHG * 256 * 65) return;
    int bh = idx / (256 * 65); int rem = idx - bh * 256 * 65;
    int j = rem / 65, d = rem % 65;
    float s = 0.f;
#pragma unroll
    for (int sp = 0; sp < NSPLIT; sp++)
        s += part[(((size_t)bh * NSPLIT + sp) * 256 + j) * 65 + d];
    ctx[((size_t)bh * 256 + j) * 68 + d] = s;
}

// ---------------- d_inv = 1 / (qp . k_sum) ----------------
__global__ void denom_kernel(const float* __restrict__ qp, const float* __restrict__ ctx,
                             float* __restrict__ dinv)
{
    int row = blockIdx.x * 8 + (threadIdx.x >> 5);
    int lane = threadIdx.x & 31;
    int bh = row >> 13;
    const float* q = qp + (size_t)row * NBF;
    const float* ks = ctx + (size_t)bh * 256 * 68 + 64;
    float s = 0.f;
#pragma unroll
    for (int i = 0; i < 8; i++) s += q[lane + i * 32] * ks[(size_t)(lane + i * 32) * 68];
#pragma unroll
    for (int o = 16; o > 0; o >>= 1) s += __shfl_xor_sync(0xffffffffu, s, o);
    if (lane == 0) dinv[row] = 1.f / s;
}

// ---------------- out_g = (qp @ ctx) * d_inv -> att ----------------
__global__ void __launch_bounds__(256) outg_kernel(
    const float* __restrict__ qp, const float* __restrict__ ctx,
    const float* __restrict__ dinv, float* __restrict__ att)
{
    __shared__ __align__(16) float Qs[32][68];
    __shared__ __align__(16) float Cs[32][68];
    int bh = blockIdx.y; int b = bh / GH, h = bh % GH;
    int n0 = blockIdx.x * 64;
    int tid = threadIdx.x;
    int tx = tid & 15, ty = tid >> 4;
    float acc[4][4] = {};
    const float* qbase = qp + ((size_t)bh * NN + n0) * NBF;
    const float* cbase = ctx + (size_t)bh * 256 * 68;
    for (int k0 = 0; k0 < 256; k0 += 32) {
        int r = tid >> 3, c4 = (tid & 7) * 4;
#pragma unroll
        for (int i = 0; i < 2; i++) {
            float4 v = *(const float4*)(qbase + (size_t)(r + i * 32) * NBF + k0 + c4);
            Qs[c4+0][r+i*32] = v.x; Qs[c4+1][r+i*32] = v.y;
            Qs[c4+2][r+i*32] = v.z; Qs[c4+3][r+i*32] = v.w;
        }
        int cr = tid >> 4, cc4 = (tid & 15) * 4;
#pragma unroll
        for (int i = 0; i < 2; i++) {
            float4 v = *(const float4*)(cbase + (size_t)(k0 + cr + i * 16) * 68 + cc4);
            *(float4*)&Cs[cr + i * 16][cc4] = v;
        }
        __syncthreads();
#pragma unroll
        for (int kk = 0; kk < 32; kk++) {
            float4 a  = *(const float4*)&Qs[kk][ty*4];
            float4 bv = *(const float4*)&Cs[kk][tx*4];
            float av[4] = {a.x,a.y,a.z,a.w}, bb[4] = {bv.x,bv.y,bv.z,bv.w};
#pragma unroll
            for (int i = 0; i < 4; i++)
#pragma unroll
                for (int j = 0; j < 4; j++) acc[i][j] += av[i] * bb[j];
        }
        __syncthreads();
    }
#pragma unroll
    for (int i = 0; i < 4; i++) {
        int n = n0 + ty * 4 + i;
        float di = dinv[(size_t)bh * NN + n];
        float4 o = {acc[i][0]*di, acc[i][1]*di, acc[i][2]*di, acc[i][3]*di};
        *(float4*)(att + ((size_t)b * NN + n) * DIMM + h * 64 + tx * 4) = o;
    }
}

// ---------------- RoPE for local heads ----------------
__global__ void rope_kernel(const float* __restrict__ q, const float* __restrict__ k,
                            float* __restrict__ rq, float* __restrict__ rk)
{
    int idx = blockIdx.x * blockDim.x + threadIdx.x;
    int i = idx & 31;
    int n = (idx >> 5) & (NN - 1);
    int bh = idx >> 18;
    int b = bh >> 1, lh = bh & 1;
    float invf = (float)exp(-(double)(2 * i) / 64.0 * 9.210340371976184);
    float ang = (float)n * invf;
    float s, c;
    sincosf(ang, &s, &c);
    size_t base = ((size_t)b * NN + n) * DIMM + (GH + lh) * 64;
    float q1 = q[base + i], q2 = q[base + 32 + i];
    float k1 = k[base + i], k2 = k[base + 32 + i];
    size_t ob = ((size_t)bh * NN + n) * DH;
    rq[ob + i]      = q1 * c - q2 * s;
    rq[ob + 32 + i] = q2 * c + q1 * s;
    rk[ob + i]      = k1 * c - k2 * s;
    rk[ob + 32 + i] = k2 * c + k1 * s;
}

// ---------------- local scores = 0.125 * bq @ bk3^T with masking ----------------
__global__ void __launch_bounds__(256) lscore_kernel(
    const float* __restrict__ rq, const float* __restrict__ rk, float* __restrict__ sc)
{
    __shared__ __align__(16) float Qs[64][68];
    __shared__ __align__(16) float Ks[64][68];
    int bw = blockIdx.z; int bh = bw >> 5; int w = bw & 31;
    int m0 = blockIdx.y * 64, c0 = blockIdx.x * 64;
    int tid = threadIdx.x;
    int lr = tid >> 2, lc4 = (tid & 3) * 4;
    const float* qb = rq + ((size_t)bh * NN + w * WINSZ + m0) * DH;
    const float* kb = rk + (size_t)bh * NN * DH;
    int knr = (w - 1) * WINSZ + c0 + lr;
    bool kvalid = (unsigned)knr < (unsigned)NN;
#pragma unroll
    for (int i = 0; i < 4; i++) {
        int c = lc4 + i * 16;
        float4 va = *(const float4*)(qb + (size_t)lr * DH + c);
        Qs[c+0][lr] = va.x; Qs[c+1][lr] = va.y; Qs[c+2][lr] = va.z; Qs[c+3][lr] = va.w;
        float4 vk = make_float4(0.f, 0.f, 0.f, 0.f);
        if (kvalid) vk = *(const float4*)(kb + (size_t)knr * DH + c);
        Ks[c+0][lr] = vk.x; Ks[c+1][lr] = vk.y; Ks[c+2][lr] = vk.z; Ks[c+3][lr] = vk.w;
    }
    __syncthreads();
    int tx = tid & 15, ty = tid >> 4;
    float acc[4][4] = {};
#pragma unroll
    for (int kk = 0; kk < 64; kk++) {
        float4 a  = *(const float4*)&Qs[kk][ty*4];
        float4 bv = *(const float4*)&Ks[kk][tx*4];
        float av[4] = {a.x,a.y,a.z,a.w}, bb[4] = {bv.x,bv.y,bv.z,bv.w};
#pragma unroll
        for (int i = 0; i < 4; i++)
#pragma unroll
            for (int j = 0; j < 4; j++) acc[i][j] += av[i] * bb[j];
    }
    int kn0 = (w - 1) * WINSZ + c0 + tx * 4;
    bool valid = (unsigned)kn0 < (unsigned)NN;
    float* ob = sc + ((size_t)bw * WINSZ + m0) * 768 + c0;
#pragma unroll
    for (int i = 0; i < 4; i++) {
        float4 o;
        o.x = valid ? acc[i][0] * 0.125f : -1e9f;
        o.y = valid ? acc[i][1] * 0.125f : -1e9f;
        o.z = valid ? acc[i][2] * 0.125f : -1e9f;
        o.w = valid ? acc[i][3] * 0.125f : -1e9f;
        *(float4*)(ob + (size_t)(ty * 4 + i) * 768 + tx * 4) = o;
    }
}

// ---------------- row stats: m and 1/sum(exp) per score row ----------------
__global__ void rowstats_kernel(const float* __restrict__ sc,
                                float* __restrict__ rm, float* __restrict__ rs)
{
    int row = blockIdx.x * 8 + (threadIdx.x >> 5);
    int lane = threadIdx.x & 31;
    const float* r = sc + (size_t)row * 768;
    float vals[24];
    float m = -1e30f;
#pragma unroll
    for (int i = 0; i < 24; i++) { vals[i] = r[lane + i * 32]; m = fmaxf(m, vals[i]); }
#pragma unroll
    for (int o = 16; o > 0; o >>= 1) m = fmaxf(m, __shfl_xor_sync(0xffffffffu, m, o));
    float s = 0.f;
#pragma unroll
    for (int i = 0; i < 24; i++) s += expf(vals[i] - m);
#pragma unroll
    for (int o = 16; o > 0; o >>= 1) s += __shfl_xor_sync(0xffffffffu, s, o);
    if (lane == 0) { rm[row] = m; rs[row] = 1.f / s; }
}

// ---------------- out_l = softmax(sc) @ bv3 -> att (exp fused in load) ----------------
__global__ void __launch_bounds__(256) outl_kernel(
    const float* __restrict__ sc, const float* __restrict__ rm, const float* __restrict__ rs,
    const float* __restrict__ v, float* __restrict__ att)
{
    __shared__ __align__(16) float As[32][68];
    __shared__ __align__(16) float Vs[32][68];
    __shared__ float sm_m[64], sm_is[64];
    int bw = blockIdx.y; int bh = bw >> 5; int w = bw & 31;
    int b = bh >> 1, lh = bh & 1;
    int m0 = blockIdx.x * 64;
    int tid = threadIdx.x;
    int tx = tid & 15, ty = tid >> 4;
    int rowbase = bw * WINSZ + m0;
    if (tid < 64) { sm_m[tid] = rm[rowbase + tid]; sm_is[tid] = rs[rowbase + tid]; }
    __syncthreads();
    float acc[4][4] = {};
    const float* sb = sc + (size_t)rowbase * 768;
    const float* vb = v + (size_t)b * NN * DIMM + (GH + lh) * 64;
    for (int k0 = 0; k0 < 768; k0 += 32) {
#pragma unroll
        for (int i = 0; i < 2; i++) {
            int s1 = tid + i * 256;
            {
                int r = s1 >> 3, c4 = (s1 & 7) * 4;
                float4 a = *(const float4*)(sb + (size_t)r * 768 + k0 + c4);
                float mm = sm_m[r], is = sm_is[r];
                As[c4+0][r] = expf(a.x - mm) * is;
                As[c4+1][r] = expf(a.y - mm) * is;
                As[c4+2][r] = expf(a.z - mm) * is;
                As[c4+3][r] = expf(a.w - mm) * is;
            }
            {
                int kr = s1 >> 4, c4 = (s1 & 15) * 4;
                int kn = (w - 1) * WINSZ + k0 + kr;
                float4 vv = make_float4(0.f, 0.f, 0.f, 0.f);
                if ((unsigned)kn < (unsigned)NN)
                    vv = *(const float4*)(vb + (size_t)kn * DIMM + c4);
                *(float4*)&Vs[kr][c4] = vv;
            }
        }
        __syncthreads();
#pragma unroll
        for (int kk = 0; kk < 32; kk++) {
            float4 a  = *(const float4*)&As[kk][ty*4];
            float4 bv = *(const float4*)&Vs[kk][tx*4];
            float av[4] = {a.x,a.y,a.z,a.w}, bb[4] = {bv.x,bv.y,bv.z,bv.w};
#pragma unroll
            for (int i = 0; i < 4; i++)
#pragma unroll
                for (int j = 0; j < 4; j++) acc[i][j] += av[i] * bb[j];
        }
        __syncthreads();
    }
#pragma unroll
    for (int i = 0; i < 4; i++) {
        int n = w * WINSZ + m0 + ty * 4 + i;
        float4 o = {acc[i][0], acc[i][1], acc[i][2], acc[i][3]};
        *(float4*)(att + ((size_t)b * NN + n) * DIMM + (GH + lh) * 64 + tx * 4) = o;
    }
}

// ---------------- launcher ----------------
extern "C" void kernel_launch(void* const* d_in, const int* in_sizes, int n_in,
                              void* d_out, int out_size)
{
    (void)in_sizes; (void)n_in; (void)out_size;
    const float* x    = (const float*)d_in[0];
    const float* Wq   = (const float*)d_in[1];
    const float* Wk   = (const float*)d_in[2];
    const float* Wv   = (const float*)d_in[3];
    const float* Wo   = (const float*)d_in[4];
    const float* bo   = (const float*)d_in[5];
    const float* proj = (const float*)d_in[6];
    float* out = (float*)d_out;

    float *q, *k, *v, *qp, *kp, *kdg, *kmp, *km, *part, *ctx, *dinv, *att, *sc, *rq, *rk, *rm, *rs, *w;
    __nv_bfloat16 *wh, *wl, *xh, *xl, *ath, *atl;
    cudaGetSymbolAddress((void**)&q, g_q);
    cudaGetSymbolAddress((void**)&k, g_k);
    cudaGetSymbolAddress((void**)&v, g_v);
    cudaGetSymbolAddress((void**)&qp, g_qp);
    cudaGetSymbolAddress((void**)&kp, g_kp);
    cudaGetSymbolAddress((void**)&kdg, g_kdiag);
    cudaGetSymbolAddress((void**)&kmp, g_kmaxp);
    cudaGetSymbolAddress((void**)&km, g_kmax);
    cudaGetSymbolAddress((void**)&part, g_part);
    cudaGetSymbolAddress((void**)&ctx, g_ctx);
    cudaGetSymbolAddress((void**)&dinv, g_dinv);
    cudaGetSymbolAddress((void**)&att, g_att);
    cudaGetSymbolAddress((void**)&sc, g_sc);
    cudaGetSymbolAddress((void**)&rq, g_rq);
    cudaGetSymbolAddress((void**)&rk, g_rk);
    cudaGetSymbolAddress((void**)&rm, g_rowm);
    cudaGetSymbolAddress((void**)&rs, g_rows);
    cudaGetSymbolAddress((void**)&w, g_w);
    cudaGetSymbolAddress((void**)&wh, g_wh);
    cudaGetSymbolAddress((void**)&wl, g_wl);
    cudaGetSymbolAddress((void**)&xh, g_xh);
    cudaGetSymbolAddress((void**)&xl, g_xl);
    cudaGetSymbolAddress((void**)&ath, g_ath);
    cudaGetSymbolAddress((void**)&atl, g_atl);

    cudaFuncSetAttribute(gemm_bfq, cudaFuncAttributeMaxDynamicSharedMemorySize, GSMEM_BYTES);

    const int M = BB * NN; // 16384

    // weights: transpose then convert; x: convert
    dim3 tb(32, 8), tg(16, 16, 4);
    wtrans4<<<tg, tb>>>(Wq, Wk, Wv, Wo, w);
    conv_hl<<<4 * 512 * 512 / 2048, 256>>>(w, wh, wl);
    conv_hl<<<(size_t)M * DIMM / 2048, 256>>>(x, xh, xl);

    // fused QKV projection (grid.x = 12 -> routes to q/k/v, 128-col blocks)
    gemm_bfq<<<dim3(12, M / 128), 256, GSMEM_BYTES>>>(xh, xl, wh, wl, nullptr, q, k, v);

    dim3 gdd(NN / 64, BHG);
    ddq_mma<<<gdd, 256>>>(q, proj, qp);
    ddk_mma<<<gdd, 256>>>(k, proj, kp, kdg, kmp);
    kmax_final_kernel<<<BHG, 128>>>(kmp, km);

    ctx_partial_kernel<<<dim3(BHG, NSPLIT), 256>>>(kp, kdg, km, v, part);
    ctx_reduce_kernel<<<(BHG * 256 * 65 + 255) / 256, 256>>>(part, ctx);

    denom_kernel<<<BHG * NN / 8, 256>>>(qp, ctx, dinv);
    outg_kernel<<<dim3(NN / 64, BHG), 256>>>(qp, ctx, dinv, att);

    rope_kernel<<<BHL * NN * 32 / 256, 256>>>(q, k, rq, rk);
    lscore_kernel<<<dim3(12, 4, BHL * NWIN), 256>>>(rq, rk, sc);
    rowstats_kernel<<<BHL * NWIN * WINSZ / 8, 256>>>(sc, rm, rs);
    outl_kernel<<<dim3(4, BHL * NWIN), 256>>>(sc, rm, rs, v, att);

    // output projection
    conv_hl<<<(size_t)M * DIMM / 2048, 256>>>(att, ath, atl);
    gemm_bfq<<<dim3(4, M / 128), 256, GSMEM_BYTES>>>(ath, atl, wh + 3 * 512 * 512, wl + 3 * 512 * 512,
                                                     bo, out, out, out);
}

// round 15
// speedup vs baseline: 1.0037x; 1.0037x over previous
#include <cuda_runtime.h>
#include <cuda_bf16.h>
#include <math.h>
#include <stdint.h>

#define BB 2
#define NN 8192
#define DIMM 512
#define GH 6
#define DH 64
#define NBF 256
#define NWIN 32
#define WINSZ 256
#define BHG (BB*GH)      // 12
#define BHL 4            // B * LOCAL_HEADS
#define NSPLIT 32

// ---------------- scratch (device globals: alloc-free) ----------------
__device__ float g_q[BB*NN*DIMM];
__device__ float g_k[BB*NN*DIMM];
__device__ float g_v[BB*NN*DIMM];
__device__ float g_qp[BHG*NN*NBF];
__device__ float g_kp[BHG*NN*NBF];      // raw k dd scores
__device__ float g_kdiag[BHG*NN];
__device__ float g_kmaxp[BHG*128];
__device__ float g_kmax[BHG];
__device__ float g_part[BHG*NSPLIT*256*65];
__device__ float g_ctx[BHG*256*68];
__device__ float g_dinv[BHG*NN];
__device__ float g_att[BB*NN*DIMM];
__device__ float g_rq[BHL*NN*DH];
__device__ float g_rk[BHL*NN*DH];
__device__ float g_w[4*512*512];                 // transposed weights fp32 (Q,K,V,O)
__device__ __nv_bfloat16 g_wh[4*512*512];        // bf16 hi
__device__ __nv_bfloat16 g_wl[4*512*512];        // bf16 lo
__device__ __nv_bfloat16 g_xh[BB*NN*DIMM];
__device__ __nv_bfloat16 g_xl[BB*NN*DIMM];
__device__ __nv_bfloat16 g_ath[BB*NN*DIMM];
__device__ __nv_bfloat16 g_atl[BB*NN*DIMM];

// ================= bf16 hi/lo split helpers =================
__device__ __forceinline__ void cvt_hl(float f0, float f1, uint32_t& hi, uint32_t& lo) {
    __nv_bfloat16 h0 = __float2bfloat16_rn(f0), h1 = __float2bfloat16_rn(f1);
    float r0 = f0 - __bfloat162float(h0), r1 = f1 - __bfloat162float(h1);
    __nv_bfloat162 hh; hh.x = h0; hh.y = h1;
    __nv_bfloat162 ll = __floats2bfloat162_rn(r0, r1);
    hi = *reinterpret_cast<uint32_t*>(&hh);
    lo = *reinterpret_cast<uint32_t*>(&ll);
}
__device__ __forceinline__ void mma_bf16(float* c, const uint32_t* a, const uint32_t* b) {
    asm volatile(
        "mma.sync.aligned.m16n8k16.row.col.f32.bf16.bf16.f32 "
        "{%0,%1,%2,%3}, {%4,%5,%6,%7}, {%8,%9}, {%0,%1,%2,%3};"
        : "+f"(c[0]), "+f"(c[1]), "+f"(c[2]), "+f"(c[3])
        : "r"(a[0]), "r"(a[1]), "r"(a[2]), "r"(a[3]), "r"(b[0]), "r"(b[1]));
}
__device__ __forceinline__ uint32_t cvta_smem(const void* p) {
    uint32_t a;
    asm("{ .reg .u64 t; cvta.to.shared.u64 t, %1; cvt.u32.u64 %0, t; }" : "=r"(a) : "l"(p));
    return a;
}
__device__ __forceinline__ void ldsm_x4(uint32_t addr, uint32_t* d) {
    asm volatile("ldmatrix.sync.aligned.m8n8.x4.shared.b16 {%0,%1,%2,%3}, [%4];"
        : "=r"(d[0]), "=r"(d[1]), "=r"(d[2]), "=r"(d[3]) : "r"(addr));
}
__device__ __forceinline__ void cp16(uint32_t s, const void* g) {
    asm volatile("cp.async.cg.shared.global [%0], [%1], 16;" :: "r"(s), "l"(g));
}
#define CP_COMMIT() asm volatile("cp.async.commit_group;" ::: "memory")
#define CP_WAIT1()  asm volatile("cp.async.wait_group 1;" ::: "memory")
#define CP_WAIT0()  asm volatile("cp.async.wait_group 0;" ::: "memory")

// ================= weight transpose (all 4 in one launch) =================
__global__ void wtrans4(const float* __restrict__ W0, const float* __restrict__ W1,
                        const float* __restrict__ W2, const float* __restrict__ W3,
                        float* __restrict__ wout)
{
    __shared__ float t[32][33];
    const float* W = (blockIdx.z == 0) ? W0 : (blockIdx.z == 1) ? W1 : (blockIdx.z == 2) ? W2 : W3;
    float* out = wout + (size_t)blockIdx.z * 512 * 512;
    int n0 = blockIdx.x * 32, k0 = blockIdx.y * 32;
    int tx = threadIdx.x, ty = threadIdx.y;
#pragma unroll
    for (int i = ty; i < 32; i += 8) t[i][tx] = W[(size_t)(k0 + i) * 512 + n0 + tx];
    __syncthreads();
#pragma unroll
    for (int i = ty; i < 32; i += 8) out[(size_t)(n0 + i) * 512 + k0 + tx] = t[tx][i];
}

// ================= fp32 -> bf16 hi/lo conversion (8 elems/thread) =================
__global__ void conv_hl(const float* __restrict__ in, __nv_bfloat16* __restrict__ oh,
                        __nv_bfloat16* __restrict__ ol)
{
    size_t i = ((size_t)blockIdx.x * 256 + threadIdx.x) * 8;
    float4 a = *(const float4*)(in + i), b = *(const float4*)(in + i + 4);
    float v[8] = {a.x, a.y, a.z, a.w, b.x, b.y, b.z, b.w};
    uint32_t h[4], l[4];
#pragma unroll
    for (int j = 0; j < 4; j++) cvt_hl(v[2*j], v[2*j+1], h[j], l[j]);
    *(uint4*)(oh + i) = make_uint4(h[0], h[1], h[2], h[3]);
    *(uint4*)(ol + i) = make_uint4(l[0], l[1], l[2], l[3]);
}

// ================= bf16x3 GEMM 128x64: cp.async 3-stage + ldmatrix + mma =================
#define STW 20
#define STAGE_W 7680
#define GSMEM_BYTES (3*STAGE_W*4)

__global__ void __launch_bounds__(256, 2) gemm_bfq(
    const __nv_bfloat16* __restrict__ Ah, const __nv_bfloat16* __restrict__ Al,
    const __nv_bfloat16* __restrict__ Bh, const __nv_bfloat16* __restrict__ Bl,
    const float* __restrict__ bias,
    float* __restrict__ o0, float* __restrict__ o1, float* __restrict__ o2)
{
    extern __shared__ uint32_t smw[];
    const int K = 512;
    const int NC = 16;
    int tid = threadIdx.x;
    int wid = tid >> 5, lane = tid & 31;
    int wm = wid >> 1, wn = wid & 1;
    int m0 = blockIdx.y * 128, n0 = blockIdx.x * 64;
    int r = lane >> 2, cq = lane & 3;
    int lr = lane & 7, lg = lane >> 3;
    float acc[2][4][4] = {};
    uint32_t smbase = cvta_smem(smw);
    uint32_t aoff = (uint32_t)(((wm * 32 + (lg & 1) * 8 + lr) * STW + (lg >> 1) * 4) * 4);
    uint32_t boff = (uint32_t)(((wn * 32 + (lg >> 1) * 8 + lr) * STW + (lg & 1) * 4) * 4);

    int arow = tid >> 1, acz = (tid & 1) * 16;
    int brow = tid >> 2, bcz = (tid & 3) * 8;
    const __nv_bfloat16* agh = Ah + (size_t)(m0 + arow) * K + acz;
    const __nv_bfloat16* agl = Al + (size_t)(m0 + arow) * K + acz;
    const __nv_bfloat16* bgh = Bh + (size_t)(n0 + brow) * K + bcz;
    const __nv_bfloat16* bgl = Bl + (size_t)(n0 + brow) * K + bcz;
    uint32_t as_off = (uint32_t)((arow * STW + (tid & 1) * 8) * 4);
    uint32_t bs_off = (uint32_t)((brow * STW + (tid & 3) * 4) * 4);

#define PREFETCH(s, k0) do { \
    uint32_t st = smbase + (uint32_t)(s) * (STAGE_W * 4); \
    cp16(st + as_off,                 agh + (k0)); \
    cp16(st + as_off + 16,            agh + (k0) + 8); \
    cp16(st + 2560 * 4 + as_off,      agl + (k0)); \
    cp16(st + 2560 * 4 + as_off + 16, agl + (k0) + 8); \
    cp16(st + 5120 * 4 + bs_off,      bgh + (k0)); \
    cp16(st + 6400 * 4 + bs_off,      bgl + (k0)); \
    CP_COMMIT(); \
} while (0)

#define DO_MMA(s) do { \
    uint32_t sb0 = smbase + (uint32_t)(s) * (STAGE_W * 4); \
    _Pragma("unroll") \
    for (int ks = 0; ks < 2; ks++) { \
        uint32_t kb = (uint32_t)(ks * 32); \
        uint32_t ah[2][4], al[2][4], bq[2][4], bl[2][4]; \
        _Pragma("unroll") \
        for (int mt = 0; mt < 2; mt++) { \
            ldsm_x4(sb0 + aoff + mt * (16 * STW * 4) + kb, ah[mt]); \
            ldsm_x4(sb0 + 2560 * 4 + aoff + mt * (16 * STW * 4) + kb, al[mt]); \
        } \
        _Pragma("unroll") \
        for (int p = 0; p < 2; p++) { \
            ldsm_x4(sb0 + 5120 * 4 + boff + p * (16 * STW * 4) + kb, bq[p]); \
            ldsm_x4(sb0 + 6400 * 4 + boff + p * (16 * STW * 4) + kb, bl[p]); \
        } \
        _Pragma("unroll") \
        for (int mt = 0; mt < 2; mt++) \
            _Pragma("unroll") \
            for (int nt = 0; nt < 4; nt++) { \
                const uint32_t* bh2 = &bq[nt >> 1][(nt & 1) * 2]; \
                const uint32_t* bl2 = &bl[nt >> 1][(nt & 1) * 2]; \
                mma_bf16(acc[mt][nt], ah[mt], bh2); \
                mma_bf16(acc[mt][nt], ah[mt], bl2); \
                mma_bf16(acc[mt][nt], al[mt], bh2); \
            } \
    } \
} while (0)

    PREFETCH(0, 0);
    PREFETCH(1, 32);
    for (int it = 0; it < NC; ++it) {
        if (it < NC - 1) { CP_WAIT1(); } else { CP_WAIT0(); }
        __syncthreads();
        if (it + 2 < NC) PREFETCH((it + 2) % 3, (it + 2) * 32);
        DO_MMA(it % 3);
    }

    int sel = n0 >> 9;
    int colb = n0 & 511;
    float* ob = (sel == 0) ? o0 : (sel == 1) ? o1 : o2;
#pragma unroll
    for (int mt = 0; mt < 2; mt++)
#pragma unroll
        for (int nt = 0; nt < 4; nt++) {
            int row = m0 + wm * 32 + mt * 16 + r;
            int col = colb + wn * 32 + nt * 8 + 2 * cq;
            float2 v0 = make_float2(acc[mt][nt][0], acc[mt][nt][1]);
            float2 v1 = make_float2(acc[mt][nt][2], acc[mt][nt][3]);
            if (bias) {
                float2 bv = *(const float2*)(bias + col);
                v0.x += bv.x; v0.y += bv.y;
                v1.x += bv.x; v1.y += bv.y;
            }
            *(float2*)(ob + (size_t)row * 512 + col) = v0;
            *(float2*)(ob + (size_t)(row + 8) * 512 + col) = v1;
        }
#undef PREFETCH
#undef DO_MMA
}

// ================= dd via bf16x3 mma: CTA = 64 rows x 256 features, K=64 =================
#define DSTW 12

#define DD_MAINLOOP() \
    float acc[2][8][4]; \
    _Pragma("unroll") \
    for (int i = 0; i < 2; i++) _Pragma("unroll") for (int j = 0; j < 8; j++) \
        _Pragma("unroll") for (int t = 0; t < 4; t++) acc[i][j][t] = 0.f; \
    int ar = tid >> 2, akq = (tid & 3) * 4; \
    const float* ab = data + ((size_t)b * NN + n0 + ar) * DIMM + h * 64 + akq; \
    const float* pbb = proj + (size_t)tid * 64; \
    float sumsq = 0.f; \
    for (int kc = 0; kc < 4; kc++) { \
        float4 va = *(const float4*)(ab + kc * 16); \
        float x0 = va.x * NORM, x1 = va.y * NORM, x2 = va.z * NORM, x3 = va.w * NORM; \
        sumsq += x0 * x0 + x1 * x1 + x2 * x2 + x3 * x3; \
        uint32_t ah0, al0, ah1, al1; \
        cvt_hl(x0, x1, ah0, al0); cvt_hl(x2, x3, ah1, al1); \
        float4 vb0 = *(const float4*)(pbb + kc * 16); \
        float4 vb1 = *(const float4*)(pbb + kc * 16 + 4); \
        float4 vb2 = *(const float4*)(pbb + kc * 16 + 8); \
        float4 vb3 = *(const float4*)(pbb + kc * 16 + 12); \
        float bvv[16] = {vb0.x,vb0.y,vb0.z,vb0.w, vb1.x,vb1.y,vb1.z,vb1.w, \
                         vb2.x,vb2.y,vb2.z,vb2.w, vb3.x,vb3.y,vb3.z,vb3.w}; \
        uint32_t bhv[8], blv[8]; \
        _Pragma("unroll") \
        for (int i = 0; i < 8; i++) cvt_hl(bvv[2*i], bvv[2*i+1], bhv[i], blv[i]); \
        __syncthreads(); \
        *(uint2*)(Ahs + ar * DSTW + (akq >> 1)) = make_uint2(ah0, ah1); \
        *(uint2*)(Als + ar * DSTW + (akq >> 1)) = make_uint2(al0, al1); \
        *(uint4*)(Bhs + tid * DSTW)     = make_uint4(bhv[0], bhv[1], bhv[2], bhv[3]); \
        *(uint4*)(Bhs + tid * DSTW + 4) = make_uint4(bhv[4], bhv[5], bhv[6], bhv[7]); \
        *(uint4*)(Bls + tid * DSTW)     = make_uint4(blv[0], blv[1], blv[2], blv[3]); \
        *(uint4*)(Bls + tid * DSTW + 4) = make_uint4(blv[4], blv[5], blv[6], blv[7]); \
        __syncthreads(); \
        uint32_t afh[2][4], afl[2][4]; \
        _Pragma("unroll") \
        for (int mt = 0; mt < 2; mt++) { \
            int mr = (wm * 32 + mt * 16 + r) * DSTW + cq; \
            afh[mt][0] = Ahs[mr];       afh[mt][1] = Ahs[mr + 8 * DSTW]; \
            afh[mt][2] = Ahs[mr + 4];   afh[mt][3] = Ahs[mr + 8 * DSTW + 4]; \
            afl[mt][0] = Als[mr];       afl[mt][1] = Als[mr + 8 * DSTW]; \
            afl[mt][2] = Als[mr + 4];   afl[mt][3] = Als[mr + 8 * DSTW + 4]; \
        } \
        _Pragma("unroll") \
        for (int nt = 0; nt < 8; nt++) { \
            int nr = (wn * 64 + nt * 8 + r) * DSTW + cq; \
            uint32_t bf[2] = {Bhs[nr], Bhs[nr + 4]}; \
            uint32_t bg[2] = {Bls[nr], Bls[nr + 4]}; \
            _Pragma("unroll") \
            for (int mt = 0; mt < 2; mt++) { \
                mma_bf16(acc[mt][nt], afh[mt], bf); \
                mma_bf16(acc[mt][nt], afh[mt], bg); \
                mma_bf16(acc[mt][nt], afl[mt], bf); \
            } \
        } \
    }

__global__ void __launch_bounds__(256, 2) ddq_mma(
    const float* __restrict__ data, const float* __restrict__ proj, float* __restrict__ qp)
{
    __shared__ uint32_t Ahs[64*DSTW], Als[64*DSTW], Bhs[256*DSTW], Bls[256*DSTW];
    __shared__ float ssq[64][4];
    __shared__ float wred[64][4];
    __shared__ float rowbase[64];
    int bh = blockIdx.y; int b = bh / GH, h = bh % GH;
    int n0 = blockIdx.x * 64;
    int tid = threadIdx.x;
    int wid = tid >> 5, lane = tid & 31;
    int wm = wid >> 2, wn = wid & 3;
    int r = lane >> 2, cq = lane & 3;
    const float NORM = 0.35355339059327373f;

    DD_MAINLOOP();

    ssq[ar][tid & 3] = sumsq;
    float mx[2][2];
#pragma unroll
    for (int mt = 0; mt < 2; mt++)
#pragma unroll
        for (int hf = 0; hf < 2; hf++) {
            float m = -1e30f;
#pragma unroll
            for (int nt = 0; nt < 8; nt++)
                m = fmaxf(m, fmaxf(acc[mt][nt][hf*2], acc[mt][nt][hf*2+1]));
            m = fmaxf(m, __shfl_xor_sync(0xffffffffu, m, 1));
            m = fmaxf(m, __shfl_xor_sync(0xffffffffu, m, 2));
            mx[mt][hf] = m;
        }
    if (cq == 0) {
#pragma unroll
        for (int mt = 0; mt < 2; mt++)
#pragma unroll
            for (int hf = 0; hf < 2; hf++)
                wred[wm * 32 + mt * 16 + hf * 8 + r][wn] = mx[mt][hf];
    }
    __syncthreads();
    if (tid < 64) {
        float mm = fmaxf(fmaxf(wred[tid][0], wred[tid][1]), fmaxf(wred[tid][2], wred[tid][3]));
        float dg = 0.5f * (ssq[tid][0] + ssq[tid][1] + ssq[tid][2] + ssq[tid][3]);
        rowbase[tid] = dg + mm;
    }
    __syncthreads();
#pragma unroll
    for (int mt = 0; mt < 2; mt++) {
        int row_a = wm * 32 + mt * 16 + r, row_b = row_a + 8;
        float ba = rowbase[row_a], bb2 = rowbase[row_b];
        float* oa = qp + ((size_t)bh * NN + n0 + row_a) * NBF;
        float* ob = qp + ((size_t)bh * NN + n0 + row_b) * NBF;
#pragma unroll
        for (int nt = 0; nt < 8; nt++) {
            int col = wn * 64 + nt * 8 + 2 * cq;
            float2 o1, o2;
            o1.x = 0.0625f * (expf(acc[mt][nt][0] - ba) + 1e-4f);
            o1.y = 0.0625f * (expf(acc[mt][nt][1] - ba) + 1e-4f);
            o2.x = 0.0625f * (expf(acc[mt][nt][2] - bb2) + 1e-4f);
            o2.y = 0.0625f * (expf(acc[mt][nt][3] - bb2) + 1e-4f);
            *(float2*)(oa + col) = o1;
            *(float2*)(ob + col) = o2;
        }
    }
}

__global__ void __launch_bounds__(256, 2) ddk_mma(
    const float* __restrict__ data, const float* __restrict__ proj,
    float* __restrict__ kdd, float* __restrict__ kdiag, float* __restrict__ kmaxp)
{
    __shared__ uint32_t Ahs[64*DSTW], Als[64*DSTW], Bhs[256*DSTW], Bls[256*DSTW];
    __shared__ float ssq[64][4];
    __shared__ float red[8];
    int bh = blockIdx.y; int b = bh / GH, h = bh % GH;
    int n0 = blockIdx.x * 64;
    int tid = threadIdx.x;
    int wid = tid >> 5, lane = tid & 31;
    int wm = wid >> 2, wn = wid & 3;
    int r = lane >> 2, cq = lane & 3;
    const float NORM = 0.35355339059327373f;

    DD_MAINLOOP();

    ssq[ar][tid & 3] = sumsq;
    __syncthreads();
    if (tid < 64)
        kdiag[(size_t)bh * NN + n0 + tid] =
            0.5f * (ssq[tid][0] + ssq[tid][1] + ssq[tid][2] + ssq[tid][3]);
    float tmax = -1e30f;
#pragma unroll
    for (int mt = 0; mt < 2; mt++) {
        int row_a = wm * 32 + mt * 16 + r, row_b = row_a + 8;
        float* oa = kdd + ((size_t)bh * NN + n0 + row_a) * NBF;
        float* ob = kdd + ((size_t)bh * NN + n0 + row_b) * NBF;
#pragma unroll
        for (int nt = 0; nt < 8; nt++) {
            int col = wn * 64 + nt * 8 + 2 * cq;
            float2 o1 = make_float2(acc[mt][nt][0], acc[mt][nt][1]);
            float2 o2 = make_float2(acc[mt][nt][2], acc[mt][nt][3]);
            tmax = fmaxf(tmax, fmaxf(fmaxf(o1.x, o1.y), fmaxf(o2.x, o2.y)));
            *(float2*)(oa + col) = o1;
            *(float2*)(ob + col) = o2;
        }
    }
#pragma unroll
    for (int o = 16; o > 0; o >>= 1) tmax = fmaxf(tmax, __shfl_xor_sync(0xffffffffu, tmax, o));
    if (lane == 0) red[wid] = tmax;
    __syncthreads();
    if (tid == 0) {
        float z = red[0];
#pragma unroll
        for (int i = 1; i < 8; i++) z = fmaxf(z, red[i]);
        kmaxp[bh * 128 + blockIdx.x] = z;
    }
}

__global__ void kmax_final_kernel(const float* __restrict__ kpart, float* __restrict__ kmax)
{
    int bh = blockIdx.x;
    float m = kpart[bh * 128 + threadIdx.x];
#pragma unroll
    for (int o = 16; o > 0; o >>= 1) m = fmaxf(m, __shfl_xor_sync(0xffffffffu, m, o));
    __shared__ float red[4];
    if ((threadIdx.x & 31) == 0) red[threadIdx.x >> 5] = m;
    __syncthreads();
    if (threadIdx.x == 0)
        kmax[bh] = fmaxf(fmaxf(red[0], red[1]), fmaxf(red[2], red[3]));
}

// ---------------- ctx: exp applied inline on raw kdd ----------------
__global__ void __launch_bounds__(256) ctx_partial_kernel(
    const float* __restrict__ kdd, const float* __restrict__ kdiag,
    const float* __restrict__ kmax, const float* __restrict__ v, float* __restrict__ part)
{
    int bh = blockIdx.x, sp = blockIdx.y;
    int b = bh / GH, h = bh % GH;
    int j = threadIdx.x;
    float acc[65];
#pragma unroll
    for (int d = 0; d < 65; d++) acc[d] = 0.f;
    __shared__ __align__(16) float vs[16][68];
    float km = kmax[bh];
    const float* kpb = kdd + ((size_t)bh * NN + sp * 256) * NBF + j;
    const float* dgb = kdiag + (size_t)bh * NN + sp * 256;
    const float* vb = v + ((size_t)b * NN + sp * 256) * DIMM + h * 64;
    for (int n0 = 0; n0 < 256; n0 += 16) {
        __syncthreads();
        int r = threadIdx.x >> 4;
        int c = (threadIdx.x & 15) * 4;
        float4 vv = *(const float4*)(vb + (size_t)(n0 + r) * DIMM + c);
        *(float4*)&vs[r][c] = vv;
        if ((threadIdx.x & 15) == 0) vs[r][64] = 1.f;
        if ((threadIdx.x & 15) == 1) vs[r][65] = dgb[n0 + r];
        __syncthreads();
#pragma unroll 2
        for (int nn = 0; nn < 16; nn++) {
            float praw = kpb[(size_t)(n0 + nn) * NBF];
            float p = 0.0625f * (expf(praw - vs[nn][65] - km) + 1e-4f);
#pragma unroll
            for (int d = 0; d < 65; d++) acc[d] += p * vs[nn][d];
        }
    }
    float* o = part + (((size_t)bh * NSPLIT + sp) * 256 + j) * 65;
#pragma unroll
    for (int d = 0; d < 65; d++) o[d] = acc[d];
}
__global__ void ctx_reduce_kernel(const float* __restrict__ part, float* __restrict__ ctx)
{
    int idx = blockIdx.x * 256 + threadIdx.x;
    if (idx >= BHG * 256 * 65) return;
    int bh = idx / (256 * 65); int rem = idx - bh * 256 * 65;
    int j = rem / 65, d = rem % 65;
    float s = 0.f;
#pragma unroll
    for (int sp = 0; sp < NSPLIT; sp++)
        s += part[(((size_t)bh * NSPLIT + sp) * 256 + j) * 65 + d];
    ctx[((size_t)bh * 256 + j) * 68 + d] = s;
}

// ---------------- d_inv = 1 / (qp . k_sum) ----------------
__global__ void denom_kernel(const float* __restrict__ qp, const float* __restrict__ ctx,
                             float* __restrict__ dinv)
{
    int row = blockIdx.x * 8 + (threadIdx.x >> 5);
    int lane = threadIdx.x & 31;
    int bh = row >> 13;
    const float* q = qp + (size_t)row * NBF;
    const float* ks = ctx + (size_t)bh * 256 * 68 + 64;
    float s = 0.f;
#pragma unroll
    for (int i = 0; i < 8; i++) s += q[lane + i * 32] * ks[(size_t)(lane + i * 32) * 68];
#pragma unroll
    for (int o = 16; o > 0; o >>= 1) s += __shfl_xor_sync(0xffffffffu, s, o);
    if (lane == 0) dinv[row] = 1.f / s;
}

// ---------------- out_g = (qp @ ctx) * d_inv -> att ----------------
__global__ void __launch_bounds__(256) outg_kernel(
    const float* __restrict__ qp, const float* __restrict__ ctx,
    const float* __restrict__ dinv, float* __restrict__ att)
{
    __shared__ __align__(16) float Qs[32][68];
    __shared__ __align__(16) float Cs[32][68];
    int bh = blockIdx.y; int b = bh / GH, h = bh % GH;
    int n0 = blockIdx.x * 64;
    int tid = threadIdx.x;
    int tx = tid & 15, ty = tid >> 4;
    float acc[4][4] = {};
    const float* qbase = qp + ((size_t)bh * NN + n0) * NBF;
    const float* cbase = ctx + (size_t)bh * 256 * 68;
    for (int k0 = 0; k0 < 256; k0 += 32) {
        int r = tid >> 3, c4 = (tid & 7) * 4;
#pragma unroll
        for (int i = 0; i < 2; i++) {
            float4 v = *(const float4*)(qbase + (size_t)(r + i * 32) * NBF + k0 + c4);
            Qs[c4+0][r+i*32] = v.x; Qs[c4+1][r+i*32] = v.y;
            Qs[c4+2][r+i*32] = v.z; Qs[c4+3][r+i*32] = v.w;
        }
        int cr = tid >> 4, cc4 = (tid & 15) * 4;
#pragma unroll
        for (int i = 0; i < 2; i++) {
            float4 v = *(const float4*)(cbase + (size_t)(k0 + cr + i * 16) * 68 + cc4);
            *(float4*)&Cs[cr + i * 16][cc4] = v;
        }
        __syncthreads();
#pragma unroll
        for (int kk = 0; kk < 32; kk++) {
            float4 a  = *(const float4*)&Qs[kk][ty*4];
            float4 bv = *(const float4*)&Cs[kk][tx*4];
            float av[4] = {a.x,a.y,a.z,a.w}, bb[4] = {bv.x,bv.y,bv.z,bv.w};
#pragma unroll
            for (int i = 0; i < 4; i++)
#pragma unroll
                for (int j = 0; j < 4; j++) acc[i][j] += av[i] * bb[j];
        }
        __syncthreads();
    }
#pragma unroll
    for (int i = 0; i < 4; i++) {
        int n = n0 + ty * 4 + i;
        float di = dinv[(size_t)bh * NN + n];
        float4 o = {acc[i][0]*di, acc[i][1]*di, acc[i][2]*di, acc[i][3]*di};
        *(float4*)(att + ((size_t)b * NN + n) * DIMM + h * 64 + tx * 4) = o;
    }
}

// ---------------- RoPE for local heads ----------------
__global__ void rope_kernel(const float* __restrict__ q, const float* __restrict__ k,
                            float* __restrict__ rq, float* __restrict__ rk)
{
    int idx = blockIdx.x * blockDim.x + threadIdx.x;
    int i = idx & 31;
    int n = (idx >> 5) & (NN - 1);
    int bh = idx >> 18;
    int b = bh >> 1, lh = bh & 1;
    float invf = (float)exp(-(double)(2 * i) / 64.0 * 9.210340371976184);
    float ang = (float)n * invf;
    float s, c;
    sincosf(ang, &s, &c);
    size_t base = ((size_t)b * NN + n) * DIMM + (GH + lh) * 64;
    float q1 = q[base + i], q2 = q[base + 32 + i];
    float k1 = k[base + i], k2 = k[base + 32 + i];
    size_t ob = ((size_t)bh * NN + n) * DH;
    rq[ob + i]      = q1 * c - q2 * s;
    rq[ob + 32 + i] = q2 * c + q1 * s;
    rk[ob + i]      = k1 * c - k2 * s;
    rk[ob + 32 + i] = k2 * c + k1 * s;
}

// ======== fused local attention: flash-style, 64 q-rows per CTA ========
// dynamic smem layout (floats): Qs[64*68] | KP[64*68] (K then aliased by P) | Vs[64*68] | rowm[64] | rowsum[64]
#define FL_Q 0
#define FL_KP (64*68)
#define FL_V (2*64*68)
#define FL_RM (3*64*68)
#define FL_RS (3*64*68 + 64)
#define FL_SMEM ((3*64*68 + 128) * 4)

__global__ void __launch_bounds__(256) flashlocal(
    const float* __restrict__ rq, const float* __restrict__ rk,
    const float* __restrict__ v, float* __restrict__ att)
{
    extern __shared__ float sm[];
    float* Qs = sm + FL_Q;    // [k][row] stride 68
    float* KP = sm + FL_KP;   // K: [k][key] stride 68; later P: [row][key] stride 68
    float* Vs = sm + FL_V;    // [key][d] stride 68
    float* rowm = sm + FL_RM;
    float* rowsum = sm + FL_RS;
    int bw = blockIdx.y; int bh = bw >> 5; int w = bw & 31;
    int b = bh >> 1, lh = bh & 1;
    int m0 = blockIdx.x * 64;
    int tid = threadIdx.x;
    int tx = tid & 15, ty = tid >> 4;
    int lr = tid >> 2, lc4 = (tid & 3) * 4;

    const float* qb = rq + ((size_t)bh * NN + w * WINSZ + m0) * DH;
#pragma unroll
    for (int i = 0; i < 4; i++) {
        int c = lc4 + i * 16;
        float4 va = *(const float4*)(qb + (size_t)lr * DH + c);
        Qs[(c+0)*68 + lr] = va.x; Qs[(c+1)*68 + lr] = va.y;
        Qs[(c+2)*68 + lr] = va.z; Qs[(c+3)*68 + lr] = va.w;
    }
    if (tid < 64) { rowm[tid] = -1e30f; rowsum[tid] = 0.f; }
    float out[4][4] = {};
    __syncthreads();

    for (int c0 = 0; c0 < 768; c0 += 64) {
        int kn0 = (w - 1) * WINSZ + c0;
        if (kn0 < 0 || kn0 >= NN) continue;
        const float* kb = rk + ((size_t)bh * NN + kn0) * DH;
        const float* vb = v + ((size_t)b * NN + kn0) * DIMM + (GH + lh) * 64;
#pragma unroll
        for (int i = 0; i < 4; i++) {
            int c = lc4 + i * 16;
            float4 vk = *(const float4*)(kb + (size_t)lr * DH + c);
            KP[(c+0)*68 + lr] = vk.x; KP[(c+1)*68 + lr] = vk.y;
            KP[(c+2)*68 + lr] = vk.z; KP[(c+3)*68 + lr] = vk.w;
            float4 vv = *(const float4*)(vb + (size_t)lr * DIMM + c);
            *(float4*)&Vs[lr*68 + c] = vv;
        }
        __syncthreads();
        // S = Q @ K^T * 0.125 (64x64)
        float s4[4][4] = {};
#pragma unroll
        for (int kk = 0; kk < 64; kk++) {
            float4 a  = *(const float4*)&Qs[kk*68 + ty*4];
            float4 bq = *(const float4*)&KP[kk*68 + tx*4];
            float av[4] = {a.x,a.y,a.z,a.w}, bb[4] = {bq.x,bq.y,bq.z,bq.w};
#pragma unroll
            for (int i = 0; i < 4; i++)
#pragma unroll
                for (int j = 0; j < 4; j++) s4[i][j] += av[i] * bb[j];
        }
        // online softmax stats per row
        float f_i[4], mnew_i[4], rsum_i[4], p[4][4];
#pragma unroll
        for (int i = 0; i < 4; i++) {
            float mc = -1e30f;
#pragma unroll
            for (int j = 0; j < 4; j++) { s4[i][j] *= 0.125f; mc = fmaxf(mc, s4[i][j]); }
#pragma unroll
            for (int o = 8; o > 0; o >>= 1) mc = fmaxf(mc, __shfl_xor_sync(0xffffffffu, mc, o));
            float mold = rowm[ty*4 + i];
            float mnew = fmaxf(mold, mc);
            mnew_i[i] = mnew;
            f_i[i] = expf(mold - mnew);
            float rs = 0.f;
#pragma unroll
            for (int j = 0; j < 4; j++) { p[i][j] = expf(s4[i][j] - mnew); rs += p[i][j]; }
#pragma unroll
            for (int o = 8; o > 0; o >>= 1) rs += __shfl_xor_sync(0xffffffffu, rs, o);
            rsum_i[i] = rs;
        }
        __syncthreads();   // all reads of rowm + K done
        if (tx == 0) {
#pragma unroll
            for (int i = 0; i < 4; i++) {
                int row = ty*4 + i;
                rowm[row] = mnew_i[i];
                rowsum[row] = rowsum[row] * f_i[i] + rsum_i[i];
            }
        }
        // store P into KP (aliased): [row][key] stride 68
#pragma unroll
        for (int i = 0; i < 4; i++) {
            float4 pv = {p[i][0], p[i][1], p[i][2], p[i][3]};
            *(float4*)&KP[(ty*4 + i)*68 + tx*4] = pv;
#pragma unroll
            for (int j = 0; j < 4; j++) out[i][j] *= f_i[i];
        }
        __syncthreads();
        // out += P @ V
#pragma unroll
        for (int kk = 0; kk < 64; kk++) {
            float4 bv = *(const float4*)&Vs[kk*68 + tx*4];
            float bb[4] = {bv.x, bv.y, bv.z, bv.w};
#pragma unroll
            for (int i = 0; i < 4; i++) {
                float a = KP[(ty*4 + i)*68 + kk];
#pragma unroll
                for (int j = 0; j < 4; j++) out[i][j] += a * bb[j];
            }
        }
        __syncthreads();
    }
#pragma unroll
    for (int i = 0; i < 4; i++) {
        int n = w * WINSZ + m0 + ty * 4 + i;
        float inv = 1.f / rowsum[ty*4 + i];
        float4 o = {out[i][0]*inv, out[i][1]*inv, out[i][2]*inv, out[i][3]*inv};
        *(float4*)(att + ((size_t)b * NN + n) * DIMM + (GH + lh) * 64 + tx * 4) = o;
    }
}

// ---------------- launcher ----------------
extern "C" void kernel_launch(void* const* d_in, const int* in_sizes, int n_in,
                              void* d_out, int out_size)
{
    (void)in_sizes; (void)n_in; (void)out_size;
    const float* x    = (const float*)d_in[0];
    const float* Wq   = (const float*)d_in[1];
    const float* Wk   = (const float*)d_in[2];
    const float* Wv   = (const float*)d_in[3];
    const float* Wo   = (const float*)d_in[4];
    const float* bo   = (const float*)d_in[5];
    const float* proj = (const float*)d_in[6];
    float* out = (float*)d_out;

    float *q, *k, *v, *qp, *kp, *kdg, *kmp, *km, *part, *ctx, *dinv, *att, *rq, *rk, *w;
    __nv_bfloat16 *wh, *wl, *xh, *xl, *ath, *atl;
    cudaGetSymbolAddress((void**)&q, g_q);
    cudaGetSymbolAddress((void**)&k, g_k);
    cudaGetSymbolAddress((void**)&v, g_v);
    cudaGetSymbolAddress((void**)&qp, g_qp);
    cudaGetSymbolAddress((void**)&kp, g_kp);
    cudaGetSymbolAddress((void**)&kdg, g_kdiag);
    cudaGetSymbolAddress((void**)&kmp, g_kmaxp);
    cudaGetSymbolAddress((void**)&km, g_kmax);
    cudaGetSymbolAddress((void**)&part, g_part);
    cudaGetSymbolAddress((void**)&ctx, g_ctx);
    cudaGetSymbolAddress((void**)&dinv, g_dinv);
    cudaGetSymbolAddress((void**)&att, g_att);
    cudaGetSymbolAddress((void**)&rq, g_rq);
    cudaGetSymbolAddress((void**)&rk, g_rk);
    cudaGetSymbolAddress((void**)&w, g_w);
    cudaGetSymbolAddress((void**)&wh, g_wh);
    cudaGetSymbolAddress((void**)&wl, g_wl);
    cudaGetSymbolAddress((void**)&xh, g_xh);
    cudaGetSymbolAddress((void**)&xl, g_xl);
    cudaGetSymbolAddress((void**)&ath, g_ath);
    cudaGetSymbolAddress((void**)&atl, g_atl);

    cudaFuncSetAttribute(gemm_bfq, cudaFuncAttributeMaxDynamicSharedMemorySize, GSMEM_BYTES);
    cudaFuncSetAttribute(flashlocal, cudaFuncAttributeMaxDynamicSharedMemorySize, FL_SMEM);

    const int M = BB * NN; // 16384

    // weights: transpose then convert; x: convert
    dim3 tb(32, 8), tg(16, 16, 4);
    wtrans4<<<tg, tb>>>(Wq, Wk, Wv, Wo, w);
    conv_hl<<<4 * 512 * 512 / 2048, 256>>>(w, wh, wl);
    conv_hl<<<(size_t)M * DIMM / 2048, 256>>>(x, xh, xl);

    // fused QKV projection (grid.x = 24 -> routes to q/k/v)
    gemm_bfq<<<dim3(24, M / 128), 256, GSMEM_BYTES>>>(xh, xl, wh, wl, nullptr, q, k, v);

    dim3 gdd(NN / 64, BHG);
    ddq_mma<<<gdd, 256>>>(q, proj, qp);
    ddk_mma<<<gdd, 256>>>(k, proj, kp, kdg, kmp);
    kmax_final_kernel<<<BHG, 128>>>(kmp, km);

    ctx_partial_kernel<<<dim3(BHG, NSPLIT), 256>>>(kp, kdg, km, v, part);
    ctx_reduce_kernel<<<(BHG * 256 * 65 + 255) / 256, 256>>>(part, ctx);

    denom_kernel<<<BHG * NN / 8, 256>>>(qp, ctx, dinv);
    outg_kernel<<<dim3(NN / 64, BHG), 256>>>(qp, ctx, dinv, att);

    rope_kernel<<<BHL * NN * 32 / 256, 256>>>(q, k, rq, rk);
    flashlocal<<<dim3(4, BHL * NWIN), 256, FL_SMEM>>>(rq, rk, v, att);

    // output projection
    conv_hl<<<(size_t)M * DIMM / 2048, 256>>>(att, ath, atl);
    gemm_bfq<<<dim3(8, M / 128), 256, GSMEM_BYTES>>>(ath, atl, wh + 3 * 512 * 512, wl + 3 * 512 * 512,
                                                     bo, out, out, out);
}

// round 16
// speedup vs baseline: 1.0256x; 1.0219x over previous
#include <cuda_runtime.h>
#include <cuda_bf16.h>
#include <math.h>
#include <stdint.h>

#define BB 2
#define NN 8192
#define DIMM 512
#define GH 6
#define DH 64
#define NBF 256
#define NWIN 32
#define WINSZ 256
#define BHG (BB*GH)      // 12
#define BHL 4            // B * LOCAL_HEADS
#define NSPLIT 32

// ---------------- scratch (device globals: alloc-free) ----------------
__device__ float g_q[BB*NN*DIMM];
__device__ float g_k[BB*NN*DIMM];
__device__ float g_v[BB*NN*DIMM];
__device__ float g_qp[BHG*NN*NBF];
__device__ float g_kp[BHG*NN*NBF];      // raw k dd scores
__device__ float g_kdiag[BHG*NN];
__device__ float g_kmaxp[BHG*128];
__device__ float g_kmax[BHG];
__device__ float g_part[BHG*NSPLIT*256*65];
__device__ float g_ctx[BHG*256*68];
__device__ float g_rq[BHL*NN*DH];
__device__ float g_rk[BHL*NN*DH];
__device__ float g_w[4*512*512];                 // transposed weights fp32 (Q,K,V,O)
__device__ __nv_bfloat16 g_wh[4*512*512];        // bf16 hi
__device__ __nv_bfloat16 g_wl[4*512*512];        // bf16 lo
__device__ __nv_bfloat16 g_xh[BB*NN*DIMM];
__device__ __nv_bfloat16 g_xl[BB*NN*DIMM];
__device__ __nv_bfloat16 g_ath[BB*NN*DIMM];
__device__ __nv_bfloat16 g_atl[BB*NN*DIMM];

// ================= bf16 hi/lo split helpers =================
__device__ __forceinline__ void cvt_hl(float f0, float f1, uint32_t& hi, uint32_t& lo) {
    __nv_bfloat16 h0 = __float2bfloat16_rn(f0), h1 = __float2bfloat16_rn(f1);
    float r0 = f0 - __bfloat162float(h0), r1 = f1 - __bfloat162float(h1);
    __nv_bfloat162 hh; hh.x = h0; hh.y = h1;
    __nv_bfloat162 ll = __floats2bfloat162_rn(r0, r1);
    hi = *reinterpret_cast<uint32_t*>(&hh);
    lo = *reinterpret_cast<uint32_t*>(&ll);
}
__device__ __forceinline__ void mma_bf16(float* c, const uint32_t* a, const uint32_t* b) {
    asm volatile(
        "mma.sync.aligned.m16n8k16.row.col.f32.bf16.bf16.f32 "
        "{%0,%1,%2,%3}, {%4,%5,%6,%7}, {%8,%9}, {%0,%1,%2,%3};"
        : "+f"(c[0]), "+f"(c[1]), "+f"(c[2]), "+f"(c[3])
        : "r"(a[0]), "r"(a[1]), "r"(a[2]), "r"(a[3]), "r"(b[0]), "r"(b[1]));
}
__device__ __forceinline__ uint32_t cvta_smem(const void* p) {
    uint32_t a;
    asm("{ .reg .u64 t; cvta.to.shared.u64 t, %1; cvt.u32.u64 %0, t; }" : "=r"(a) : "l"(p));
    return a;
}
__device__ __forceinline__ void ldsm_x4(uint32_t addr, uint32_t* d) {
    asm volatile("ldmatrix.sync.aligned.m8n8.x4.shared.b16 {%0,%1,%2,%3}, [%4];"
        : "=r"(d[0]), "=r"(d[1]), "=r"(d[2]), "=r"(d[3]) : "r"(addr));
}
__device__ __forceinline__ void cp16(uint32_t s, const void* g) {
    asm volatile("cp.async.cg.shared.global [%0], [%1], 16;" :: "r"(s), "l"(g));
}
#define CP_COMMIT() asm volatile("cp.async.commit_group;" ::: "memory")
#define CP_WAIT1()  asm volatile("cp.async.wait_group 1;" ::: "memory")
#define CP_WAIT0()  asm volatile("cp.async.wait_group 0;" ::: "memory")

// ================= weight transpose (all 4 in one launch) =================
__global__ void wtrans4(const float* __restrict__ W0, const float* __restrict__ W1,
                        const float* __restrict__ W2, const float* __restrict__ W3,
                        float* __restrict__ wout)
{
    __shared__ float t[32][33];
    const float* W = (blockIdx.z == 0) ? W0 : (blockIdx.z == 1) ? W1 : (blockIdx.z == 2) ? W2 : W3;
    float* out = wout + (size_t)blockIdx.z * 512 * 512;
    int n0 = blockIdx.x * 32, k0 = blockIdx.y * 32;
    int tx = threadIdx.x, ty = threadIdx.y;
#pragma unroll
    for (int i = ty; i < 32; i += 8) t[i][tx] = W[(size_t)(k0 + i) * 512 + n0 + tx];
    __syncthreads();
#pragma unroll
    for (int i = ty; i < 32; i += 8) out[(size_t)(n0 + i) * 512 + k0 + tx] = t[tx][i];
}

// ================= fp32 -> bf16 hi/lo conversion (8 elems/thread) =================
__global__ void conv_hl(const float* __restrict__ in, __nv_bfloat16* __restrict__ oh,
                        __nv_bfloat16* __restrict__ ol)
{
    size_t i = ((size_t)blockIdx.x * 256 + threadIdx.x) * 8;
    float4 a = *(const float4*)(in + i), b = *(const float4*)(in + i + 4);
    float v[8] = {a.x, a.y, a.z, a.w, b.x, b.y, b.z, b.w};
    uint32_t h[4], l[4];
#pragma unroll
    for (int j = 0; j < 4; j++) cvt_hl(v[2*j], v[2*j+1], h[j], l[j]);
    *(uint4*)(oh + i) = make_uint4(h[0], h[1], h[2], h[3]);
    *(uint4*)(ol + i) = make_uint4(l[0], l[1], l[2], l[3]);
}

// ================= bf16x3 GEMM 128x64: cp.async 3-stage + ldmatrix + mma =================
#define STW 20
#define STAGE_W 7680
#define GSMEM_BYTES (3*STAGE_W*4)

__global__ void __launch_bounds__(256, 2) gemm_bfq(
    const __nv_bfloat16* __restrict__ Ah, const __nv_bfloat16* __restrict__ Al,
    const __nv_bfloat16* __restrict__ Bh, const __nv_bfloat16* __restrict__ Bl,
    const float* __restrict__ bias,
    float* __restrict__ o0, float* __restrict__ o1, float* __restrict__ o2)
{
    extern __shared__ uint32_t smw[];
    const int K = 512;
    const int NC = 16;
    int tid = threadIdx.x;
    int wid = tid >> 5, lane = tid & 31;
    int wm = wid >> 1, wn = wid & 1;
    int m0 = blockIdx.y * 128, n0 = blockIdx.x * 64;
    int r = lane >> 2, cq = lane & 3;
    int lr = lane & 7, lg = lane >> 3;
    float acc[2][4][4] = {};
    uint32_t smbase = cvta_smem(smw);
    uint32_t aoff = (uint32_t)(((wm * 32 + (lg & 1) * 8 + lr) * STW + (lg >> 1) * 4) * 4);
    uint32_t boff = (uint32_t)(((wn * 32 + (lg >> 1) * 8 + lr) * STW + (lg & 1) * 4) * 4);

    int arow = tid >> 1, acz = (tid & 1) * 16;
    int brow = tid >> 2, bcz = (tid & 3) * 8;
    const __nv_bfloat16* agh = Ah + (size_t)(m0 + arow) * K + acz;
    const __nv_bfloat16* agl = Al + (size_t)(m0 + arow) * K + acz;
    const __nv_bfloat16* bgh = Bh + (size_t)(n0 + brow) * K + bcz;
    const __nv_bfloat16* bgl = Bl + (size_t)(n0 + brow) * K + bcz;
    uint32_t as_off = (uint32_t)((arow * STW + (tid & 1) * 8) * 4);
    uint32_t bs_off = (uint32_t)((brow * STW + (tid & 3) * 4) * 4);

#define PREFETCH(s, k0) do { \
    uint32_t st = smbase + (uint32_t)(s) * (STAGE_W * 4); \
    cp16(st + as_off,                 agh + (k0)); \
    cp16(st + as_off + 16,            agh + (k0) + 8); \
    cp16(st + 2560 * 4 + as_off,      agl + (k0)); \
    cp16(st + 2560 * 4 + as_off + 16, agl + (k0) + 8); \
    cp16(st + 5120 * 4 + bs_off,      bgh + (k0)); \
    cp16(st + 6400 * 4 + bs_off,      bgl + (k0)); \
    CP_COMMIT(); \
} while (0)

#define DO_MMA(s) do { \
    uint32_t sb0 = smbase + (uint32_t)(s) * (STAGE_W * 4); \
    _Pragma("unroll") \
    for (int ks = 0; ks < 2; ks++) { \
        uint32_t kb = (uint32_t)(ks * 32); \
        uint32_t ah[2][4], al[2][4], bq[2][4], bl[2][4]; \
        _Pragma("unroll") \
        for (int mt = 0; mt < 2; mt++) { \
            ldsm_x4(sb0 + aoff + mt * (16 * STW * 4) + kb, ah[mt]); \
            ldsm_x4(sb0 + 2560 * 4 + aoff + mt * (16 * STW * 4) + kb, al[mt]); \
        } \
        _Pragma("unroll") \
        for (int p = 0; p < 2; p++) { \
            ldsm_x4(sb0 + 5120 * 4 + boff + p * (16 * STW * 4) + kb, bq[p]); \
            ldsm_x4(sb0 + 6400 * 4 + boff + p * (16 * STW * 4) + kb, bl[p]); \
        } \
        _Pragma("unroll") \
        for (int mt = 0; mt < 2; mt++) \
            _Pragma("unroll") \
            for (int nt = 0; nt < 4; nt++) { \
                const uint32_t* bh2 = &bq[nt >> 1][(nt & 1) * 2]; \
                const uint32_t* bl2 = &bl[nt >> 1][(nt & 1) * 2]; \
                mma_bf16(acc[mt][nt], ah[mt], bh2); \
                mma_bf16(acc[mt][nt], ah[mt], bl2); \
                mma_bf16(acc[mt][nt], al[mt], bh2); \
            } \
    } \
} while (0)

    PREFETCH(0, 0);
    PREFETCH(1, 32);
    for (int it = 0; it < NC; ++it) {
        if (it < NC - 1) { CP_WAIT1(); } else { CP_WAIT0(); }
        __syncthreads();
        if (it + 2 < NC) PREFETCH((it + 2) % 3, (it + 2) * 32);
        DO_MMA(it % 3);
    }

    int sel = n0 >> 9;
    int colb = n0 & 511;
    float* ob = (sel == 0) ? o0 : (sel == 1) ? o1 : o2;
#pragma unroll
    for (int mt = 0; mt < 2; mt++)
#pragma unroll
        for (int nt = 0; nt < 4; nt++) {
            int row = m0 + wm * 32 + mt * 16 + r;
            int col = colb + wn * 32 + nt * 8 + 2 * cq;
            float2 v0 = make_float2(acc[mt][nt][0], acc[mt][nt][1]);
            float2 v1 = make_float2(acc[mt][nt][2], acc[mt][nt][3]);
            if (bias) {
                float2 bv = *(const float2*)(bias + col);
                v0.x += bv.x; v0.y += bv.y;
                v1.x += bv.x; v1.y += bv.y;
            }
            *(float2*)(ob + (size_t)row * 512 + col) = v0;
            *(float2*)(ob + (size_t)(row + 8) * 512 + col) = v1;
        }
#undef PREFETCH
#undef DO_MMA
}

// ================= dd via bf16x3 mma: CTA = 64 rows x 256 features, K=64 =================
#define DSTW 12

#define DD_MAINLOOP() \
    float acc[2][8][4]; \
    _Pragma("unroll") \
    for (int i = 0; i < 2; i++) _Pragma("unroll") for (int j = 0; j < 8; j++) \
        _Pragma("unroll") for (int t = 0; t < 4; t++) acc[i][j][t] = 0.f; \
    int ar = tid >> 2, akq = (tid & 3) * 4; \
    const float* ab = data + ((size_t)b * NN + n0 + ar) * DIMM + h * 64 + akq; \
    const float* pbb = proj + (size_t)tid * 64; \
    float sumsq = 0.f; \
    for (int kc = 0; kc < 4; kc++) { \
        float4 va = *(const float4*)(ab + kc * 16); \
        float x0 = va.x * NORM, x1 = va.y * NORM, x2 = va.z * NORM, x3 = va.w * NORM; \
        sumsq += x0 * x0 + x1 * x1 + x2 * x2 + x3 * x3; \
        uint32_t ah0, al0, ah1, al1; \
        cvt_hl(x0, x1, ah0, al0); cvt_hl(x2, x3, ah1, al1); \
        float4 vb0 = *(const float4*)(pbb + kc * 16); \
        float4 vb1 = *(const float4*)(pbb + kc * 16 + 4); \
        float4 vb2 = *(const float4*)(pbb + kc * 16 + 8); \
        float4 vb3 = *(const float4*)(pbb + kc * 16 + 12); \
        float bvv[16] = {vb0.x,vb0.y,vb0.z,vb0.w, vb1.x,vb1.y,vb1.z,vb1.w, \
                         vb2.x,vb2.y,vb2.z,vb2.w, vb3.x,vb3.y,vb3.z,vb3.w}; \
        uint32_t bhv[8], blv[8]; \
        _Pragma("unroll") \
        for (int i = 0; i < 8; i++) cvt_hl(bvv[2*i], bvv[2*i+1], bhv[i], blv[i]); \
        __syncthreads(); \
        *(uint2*)(Ahs + ar * DSTW + (akq >> 1)) = make_uint2(ah0, ah1); \
        *(uint2*)(Als + ar * DSTW + (akq >> 1)) = make_uint2(al0, al1); \
        *(uint4*)(Bhs + tid * DSTW)     = make_uint4(bhv[0], bhv[1], bhv[2], bhv[3]); \
        *(uint4*)(Bhs + tid * DSTW + 4) = make_uint4(bhv[4], bhv[5], bhv[6], bhv[7]); \
        *(uint4*)(Bls + tid * DSTW)     = make_uint4(blv[0], blv[1], blv[2], blv[3]); \
        *(uint4*)(Bls + tid * DSTW + 4) = make_uint4(blv[4], blv[5], blv[6], blv[7]); \
        __syncthreads(); \
        uint32_t afh[2][4], afl[2][4]; \
        _Pragma("unroll") \
        for (int mt = 0; mt < 2; mt++) { \
            int mr = (wm * 32 + mt * 16 + r) * DSTW + cq; \
            afh[mt][0] = Ahs[mr];       afh[mt][1] = Ahs[mr + 8 * DSTW]; \
            afh[mt][2] = Ahs[mr + 4];   afh[mt][3] = Ahs[mr + 8 * DSTW + 4]; \
            afl[mt][0] = Als[mr];       afl[mt][1] = Als[mr + 8 * DSTW]; \
            afl[mt][2] = Als[mr + 4];   afl[mt][3] = Als[mr + 8 * DSTW + 4]; \
        } \
        _Pragma("unroll") \
        for (int nt = 0; nt < 8; nt++) { \
            int nr = (wn * 64 + nt * 8 + r) * DSTW + cq; \
            uint32_t bf[2] = {Bhs[nr], Bhs[nr + 4]}; \
            uint32_t bg[2] = {Bls[nr], Bls[nr + 4]}; \
            _Pragma("unroll") \
            for (int mt = 0; mt < 2; mt++) { \
                mma_bf16(acc[mt][nt], afh[mt], bf); \
                mma_bf16(acc[mt][nt], afh[mt], bg); \
                mma_bf16(acc[mt][nt], afl[mt], bf); \
            } \
        } \
    }

__global__ void __launch_bounds__(256, 2) ddq_mma(
    const float* __restrict__ data, const float* __restrict__ proj, float* __restrict__ qp)
{
    __shared__ uint32_t Ahs[64*DSTW], Als[64*DSTW], Bhs[256*DSTW], Bls[256*DSTW];
    __shared__ float ssq[64][4];
    __shared__ float wred[64][4];
    __shared__ float rowbase[64];
    int bh = blockIdx.y; int b = bh / GH, h = bh % GH;
    int n0 = blockIdx.x * 64;
    int tid = threadIdx.x;
    int wid = tid >> 5, lane = tid & 31;
    int wm = wid >> 2, wn = wid & 3;
    int r = lane >> 2, cq = lane & 3;
    const float NORM = 0.35355339059327373f;

    DD_MAINLOOP();

    ssq[ar][tid & 3] = sumsq;
    float mx[2][2];
#pragma unroll
    for (int mt = 0; mt < 2; mt++)
#pragma unroll
        for (int hf = 0; hf < 2; hf++) {
            float m = -1e30f;
#pragma unroll
            for (int nt = 0; nt < 8; nt++)
                m = fmaxf(m, fmaxf(acc[mt][nt][hf*2], acc[mt][nt][hf*2+1]));
            m = fmaxf(m, __shfl_xor_sync(0xffffffffu, m, 1));
            m = fmaxf(m, __shfl_xor_sync(0xffffffffu, m, 2));
            mx[mt][hf] = m;
        }
    if (cq == 0) {
#pragma unroll
        for (int mt = 0; mt < 2; mt++)
#pragma unroll
            for (int hf = 0; hf < 2; hf++)
                wred[wm * 32 + mt * 16 + hf * 8 + r][wn] = mx[mt][hf];
    }
    __syncthreads();
    if (tid < 64) {
        float mm = fmaxf(fmaxf(wred[tid][0], wred[tid][1]), fmaxf(wred[tid][2], wred[tid][3]));
        float dg = 0.5f * (ssq[tid][0] + ssq[tid][1] + ssq[tid][2] + ssq[tid][3]);
        rowbase[tid] = dg + mm;
    }
    __syncthreads();
#pragma unroll
    for (int mt = 0; mt < 2; mt++) {
        int row_a = wm * 32 + mt * 16 + r, row_b = row_a + 8;
        float ba = rowbase[row_a], bb2 = rowbase[row_b];
        float* oa = qp + ((size_t)bh * NN + n0 + row_a) * NBF;
        float* ob = qp + ((size_t)bh * NN + n0 + row_b) * NBF;
#pragma unroll
        for (int nt = 0; nt < 8; nt++) {
            int col = wn * 64 + nt * 8 + 2 * cq;
            float2 o1, o2;
            o1.x = 0.0625f * (expf(acc[mt][nt][0] - ba) + 1e-4f);
            o1.y = 0.0625f * (expf(acc[mt][nt][1] - ba) + 1e-4f);
            o2.x = 0.0625f * (expf(acc[mt][nt][2] - bb2) + 1e-4f);
            o2.y = 0.0625f * (expf(acc[mt][nt][3] - bb2) + 1e-4f);
            *(float2*)(oa + col) = o1;
            *(float2*)(ob + col) = o2;
        }
    }
}

__global__ void __launch_bounds__(256, 2) ddk_mma(
    const float* __restrict__ data, const float* __restrict__ proj,
    float* __restrict__ kdd, float* __restrict__ kdiag, float* __restrict__ kmaxp)
{
    __shared__ uint32_t Ahs[64*DSTW], Als[64*DSTW], Bhs[256*DSTW], Bls[256*DSTW];
    __shared__ float ssq[64][4];
    __shared__ float red[8];
    int bh = blockIdx.y; int b = bh / GH, h = bh % GH;
    int n0 = blockIdx.x * 64;
    int tid = threadIdx.x;
    int wid = tid >> 5, lane = tid & 31;
    int wm = wid >> 2, wn = wid & 3;
    int r = lane >> 2, cq = lane & 3;
    const float NORM = 0.35355339059327373f;

    DD_MAINLOOP();

    ssq[ar][tid & 3] = sumsq;
    __syncthreads();
    if (tid < 64)
        kdiag[(size_t)bh * NN + n0 + tid] =
            0.5f * (ssq[tid][0] + ssq[tid][1] + ssq[tid][2] + ssq[tid][3]);
    float tmax = -1e30f;
#pragma unroll
    for (int mt = 0; mt < 2; mt++) {
        int row_a = wm * 32 + mt * 16 + r, row_b = row_a + 8;
        float* oa = kdd + ((size_t)bh * NN + n0 + row_a) * NBF;
        float* ob = kdd + ((size_t)bh * NN + n0 + row_b) * NBF;
#pragma unroll
        for (int nt = 0; nt < 8; nt++) {
            int col = wn * 64 + nt * 8 + 2 * cq;
            float2 o1 = make_float2(acc[mt][nt][0], acc[mt][nt][1]);
            float2 o2 = make_float2(acc[mt][nt][2], acc[mt][nt][3]);
            tmax = fmaxf(tmax, fmaxf(fmaxf(o1.x, o1.y), fmaxf(o2.x, o2.y)));
            *(float2*)(oa + col) = o1;
            *(float2*)(ob + col) = o2;
        }
    }
#pragma unroll
    for (int o = 16; o > 0; o >>= 1) tmax = fmaxf(tmax, __shfl_xor_sync(0xffffffffu, tmax, o));
    if (lane == 0) red[wid] = tmax;
    __syncthreads();
    if (tid == 0) {
        float z = red[0];
#pragma unroll
        for (int i = 1; i < 8; i++) z = fmaxf(z, red[i]);
        kmaxp[bh * 128 + blockIdx.x] = z;
    }
}

__global__ void kmax_final_kernel(const float* __restrict__ kpart, float* __restrict__ kmax)
{
    int bh = blockIdx.x;
    float m = kpart[bh * 128 + threadIdx.x];
#pragma unroll
    for (int o = 16; o > 0; o >>= 1) m = fmaxf(m, __shfl_xor_sync(0xffffffffu, m, o));
    __shared__ float red[4];
    if ((threadIdx.x & 31) == 0) red[threadIdx.x >> 5] = m;
    __syncthreads();
    if (threadIdx.x == 0)
        kmax[bh] = fmaxf(fmaxf(red[0], red[1]), fmaxf(red[2], red[3]));
}

// ---------------- ctx: exp applied inline on raw kdd ----------------
__global__ void __launch_bounds__(256) ctx_partial_kernel(
    const float* __restrict__ kdd, const float* __restrict__ kdiag,
    const float* __restrict__ kmax, const float* __restrict__ v, float* __restrict__ part)
{
    int bh = blockIdx.x, sp = blockIdx.y;
    int b = bh / GH, h = bh % GH;
    int j = threadIdx.x;
    float acc[65];
#pragma unroll
    for (int d = 0; d < 65; d++) acc[d] = 0.f;
    __shared__ __align__(16) float vs[16][68];
    float km = kmax[bh];
    const float* kpb = kdd + ((size_t)bh * NN + sp * 256) * NBF + j;
    const float* dgb = kdiag + (size_t)bh * NN + sp * 256;
    const float* vb = v + ((size_t)b * NN + sp * 256) * DIMM + h * 64;
    for (int n0 = 0; n0 < 256; n0 += 16) {
        __syncthreads();
        int r = threadIdx.x >> 4;
        int c = (threadIdx.x & 15) * 4;
        float4 vv = *(const float4*)(vb + (size_t)(n0 + r) * DIMM + c);
        *(float4*)&vs[r][c] = vv;
        if ((threadIdx.x & 15) == 0) vs[r][64] = 1.f;
        if ((threadIdx.x & 15) == 1) vs[r][65] = dgb[n0 + r];
        __syncthreads();
#pragma unroll 2
        for (int nn = 0; nn < 16; nn++) {
            float praw = kpb[(size_t)(n0 + nn) * NBF];
            float p = 0.0625f * (expf(praw - vs[nn][65] - km) + 1e-4f);
#pragma unroll
            for (int d = 0; d < 65; d++) acc[d] += p * vs[nn][d];
        }
    }
    float* o = part + (((size_t)bh * NSPLIT + sp) * 256 + j) * 65;
#pragma unroll
    for (int d = 0; d < 65; d++) o[d] = acc[d];
}
__global__ void ctx_reduce_kernel(const float* __restrict__ part, float* __restrict__ ctx)
{
    int idx = blockIdx.x * 256 + threadIdx.x;
    if (idx >= BHG * 256 * 65) return;
    int bh = idx / (256 * 65); int rem = idx - bh * 256 * 65;
    int j = rem / 65, d = rem % 65;
    float s = 0.f;
#pragma unroll
    for (int sp = 0; sp < NSPLIT; sp++)
        s += part[(((size_t)bh * NSPLIT + sp) * 256 + j) * 65 + d];
    ctx[((size_t)bh * 256 + j) * 68 + d] = s;
}

// ---------------- out_g = (qp @ ctx) * d_inv -> ath/atl (denom fused) ----------------
__global__ void __launch_bounds__(256) outg_kernel(
    const float* __restrict__ qp, const float* __restrict__ ctx,
    __nv_bfloat16* __restrict__ ath, __nv_bfloat16* __restrict__ atl)
{
    __shared__ __align__(16) float Qs[32][68];
    __shared__ __align__(16) float Cs[32][68];
    __shared__ float ksum_s[32];
    int bh = blockIdx.y; int b = bh / GH, h = bh % GH;
    int n0 = blockIdx.x * 64;
    int tid = threadIdx.x;
    int tx = tid & 15, ty = tid >> 4;
    float acc[4][4] = {};
    float dsum[4] = {};
    const float* qbase = qp + ((size_t)bh * NN + n0) * NBF;
    const float* cbase = ctx + (size_t)bh * 256 * 68;
    for (int k0 = 0; k0 < 256; k0 += 32) {
        int r = tid >> 3, c4 = (tid & 7) * 4;
#pragma unroll
        for (int i = 0; i < 2; i++) {
            float4 v = *(const float4*)(qbase + (size_t)(r + i * 32) * NBF + k0 + c4);
            Qs[c4+0][r+i*32] = v.x; Qs[c4+1][r+i*32] = v.y;
            Qs[c4+2][r+i*32] = v.z; Qs[c4+3][r+i*32] = v.w;
        }
        int cr = tid >> 4, cc4 = (tid & 15) * 4;
#pragma unroll
        for (int i = 0; i < 2; i++) {
            float4 v = *(const float4*)(cbase + (size_t)(k0 + cr + i * 16) * 68 + cc4);
            *(float4*)&Cs[cr + i * 16][cc4] = v;
        }
        if (tid < 32) ksum_s[tid] = cbase[(size_t)(k0 + tid) * 68 + 64];
        __syncthreads();
#pragma unroll
        for (int kk = 0; kk < 32; kk++) {
            float4 a  = *(const float4*)&Qs[kk][ty*4];
            float4 bv = *(const float4*)&Cs[kk][tx*4];
            float ks = ksum_s[kk];
            float av[4] = {a.x,a.y,a.z,a.w}, bb[4] = {bv.x,bv.y,bv.z,bv.w};
#pragma unroll
            for (int i = 0; i < 4; i++) {
                dsum[i] += av[i] * ks;
#pragma unroll
                for (int j = 0; j < 4; j++) acc[i][j] += av[i] * bb[j];
            }
        }
        __syncthreads();
    }
#pragma unroll
    for (int i = 0; i < 4; i++) {
        int n = n0 + ty * 4 + i;
        float di = 1.f / dsum[i];
        float v0 = acc[i][0]*di, v1 = acc[i][1]*di, v2 = acc[i][2]*di, v3 = acc[i][3]*di;
        uint32_t h0, l0, h1, l1;
        cvt_hl(v0, v1, h0, l0);
        cvt_hl(v2, v3, h1, l1);
        size_t off = ((size_t)b * NN + n) * DIMM + h * 64 + tx * 4;
        *(uint2*)(ath + off) = make_uint2(h0, h1);
        *(uint2*)(atl + off) = make_uint2(l0, l1);
    }
}

// ---------------- RoPE for local heads ----------------
__global__ void rope_kernel(const float* __restrict__ q, const float* __restrict__ k,
                            float* __restrict__ rq, float* __restrict__ rk)
{
    int idx = blockIdx.x * blockDim.x + threadIdx.x;
    int i = idx & 31;
    int n = (idx >> 5) & (NN - 1);
    int bh = idx >> 18;
    int b = bh >> 1, lh = bh & 1;
    float invf = (float)exp(-(double)(2 * i) / 64.0 * 9.210340371976184);
    float ang = (float)n * invf;
    float s, c;
    sincosf(ang, &s, &c);
    size_t base = ((size_t)b * NN + n) * DIMM + (GH + lh) * 64;
    float q1 = q[base + i], q2 = q[base + 32 + i];
    float k1 = k[base + i], k2 = k[base + 32 + i];
    size_t ob = ((size_t)bh * NN + n) * DH;
    rq[ob + i]      = q1 * c - q2 * s;
    rq[ob + 32 + i] = q2 * c + q1 * s;
    rk[ob + i]      = k1 * c - k2 * s;
    rk[ob + 32 + i] = k2 * c + k1 * s;
}

// ======== fused local attention: flash-style, 64 q-rows per CTA ========
#define FL_Q 0
#define FL_KP (64*68)
#define FL_V (2*64*68)
#define FL_RM (3*64*68)
#define FL_RS (3*64*68 + 64)
#define FL_SMEM ((3*64*68 + 128) * 4)

__global__ void __launch_bounds__(256) flashlocal(
    const float* __restrict__ rq, const float* __restrict__ rk,
    const float* __restrict__ v,
    __nv_bfloat16* __restrict__ ath, __nv_bfloat16* __restrict__ atl)
{
    extern __shared__ float sm[];
    float* Qs = sm + FL_Q;
    float* KP = sm + FL_KP;
    float* Vs = sm + FL_V;
    float* rowm = sm + FL_RM;
    float* rowsum = sm + FL_RS;
    int bw = blockIdx.y; int bh = bw >> 5; int w = bw & 31;
    int b = bh >> 1, lh = bh & 1;
    int m0 = blockIdx.x * 64;
    int tid = threadIdx.x;
    int tx = tid & 15, ty = tid >> 4;
    int lr = tid >> 2, lc4 = (tid & 3) * 4;

    const float* qb = rq + ((size_t)bh * NN + w * WINSZ + m0) * DH;
#pragma unroll
    for (int i = 0; i < 4; i++) {
        int c = lc4 + i * 16;
        float4 va = *(const float4*)(qb + (size_t)lr * DH + c);
        Qs[(c+0)*68 + lr] = va.x; Qs[(c+1)*68 + lr] = va.y;
        Qs[(c+2)*68 + lr] = va.z; Qs[(c+3)*68 + lr] = va.w;
    }
    if (tid < 64) { rowm[tid] = -1e30f; rowsum[tid] = 0.f; }
    float out[4][4] = {};
    __syncthreads();

    for (int c0 = 0; c0 < 768; c0 += 64) {
        int kn0 = (w - 1) * WINSZ + c0;
        if (kn0 < 0 || kn0 >= NN) continue;
        const float* kb = rk + ((size_t)bh * NN + kn0) * DH;
        const float* vb = v + ((size_t)b * NN + kn0) * DIMM + (GH + lh) * 64;
#pragma unroll
        for (int i = 0; i < 4; i++) {
            int c = lc4 + i * 16;
            float4 vk = *(const float4*)(kb + (size_t)lr * DH + c);
            KP[(c+0)*68 + lr] = vk.x; KP[(c+1)*68 + lr] = vk.y;
            KP[(c+2)*68 + lr] = vk.z; KP[(c+3)*68 + lr] = vk.w;
            float4 vv = *(const float4*)(vb + (size_t)lr * DIMM + c);
            *(float4*)&Vs[lr*68 + c] = vv;
        }
        __syncthreads();
        float s4[4][4] = {};
#pragma unroll
        for (int kk = 0; kk < 64; kk++) {
            float4 a  = *(const float4*)&Qs[kk*68 + ty*4];
            float4 bq = *(const float4*)&KP[kk*68 + tx*4];
            float av[4] = {a.x,a.y,a.z,a.w}, bb[4] = {bq.x,bq.y,bq.z,bq.w};
#pragma unroll
            for (int i = 0; i < 4; i++)
#pragma unroll
                for (int j = 0; j < 4; j++) s4[i][j] += av[i] * bb[j];
        }
        float f_i[4], mnew_i[4], rsum_i[4], p[4][4];
#pragma unroll
        for (int i = 0; i < 4; i++) {
            float mc = -1e30f;
#pragma unroll
            for (int j = 0; j < 4; j++) { s4[i][j] *= 0.125f; mc = fmaxf(mc, s4[i][j]); }
#pragma unroll
            for (int o = 8; o > 0; o >>= 1) mc = fmaxf(mc, __shfl_xor_sync(0xffffffffu, mc, o));
            float mold = rowm[ty*4 + i];
            float mnew = fmaxf(mold, mc);
            mnew_i[i] = mnew;
            f_i[i] = expf(mold - mnew);
            float rs = 0.f;
#pragma unroll
            for (int j = 0; j < 4; j++) { p[i][j] = expf(s4[i][j] - mnew); rs += p[i][j]; }
#pragma unroll
            for (int o = 8; o > 0; o >>= 1) rs += __shfl_xor_sync(0xffffffffu, rs, o);
            rsum_i[i] = rs;
        }
        __syncthreads();
        if (tx == 0) {
#pragma unroll
            for (int i = 0; i < 4; i++) {
                int row = ty*4 + i;
                rowm[row] = mnew_i[i];
                rowsum[row] = rowsum[row] * f_i[i] + rsum_i[i];
            }
        }
#pragma unroll
        for (int i = 0; i < 4; i++) {
            float4 pv = {p[i][0], p[i][1], p[i][2], p[i][3]};
            *(float4*)&KP[(ty*4 + i)*68 + tx*4] = pv;
#pragma unroll
            for (int j = 0; j < 4; j++) out[i][j] *= f_i[i];
        }
        __syncthreads();
#pragma unroll
        for (int kk = 0; kk < 64; kk++) {
            float4 bv = *(const float4*)&Vs[kk*68 + tx*4];
            float bb[4] = {bv.x, bv.y, bv.z, bv.w};
#pragma unroll
            for (int i = 0; i < 4; i++) {
                float a = KP[(ty*4 + i)*68 + kk];
#pragma unroll
                for (int j = 0; j < 4; j++) out[i][j] += a * bb[j];
            }
        }
        __syncthreads();
    }
#pragma unroll
    for (int i = 0; i < 4; i++) {
        int n = w * WINSZ + m0 + ty * 4 + i;
        float inv = 1.f / rowsum[ty*4 + i];
        float v0 = out[i][0]*inv, v1 = out[i][1]*inv, v2 = out[i][2]*inv, v3 = out[i][3]*inv;
        uint32_t h0, l0, h1, l1;
        cvt_hl(v0, v1, h0, l0);
        cvt_hl(v2, v3, h1, l1);
        size_t off = ((size_t)b * NN + n) * DIMM + (GH + lh) * 64 + tx * 4;
        *(uint2*)(ath + off) = make_uint2(h0, h1);
        *(uint2*)(atl + off) = make_uint2(l0, l1);
    }
}

// ---------------- launcher ----------------
extern "C" void kernel_launch(void* const* d_in, const int* in_sizes, int n_in,
                              void* d_out, int out_size)
{
    (void)in_sizes; (void)n_in; (void)out_size;
    const float* x    = (const float*)d_in[0];
    const float* Wq   = (const float*)d_in[1];
    const float* Wk   = (const float*)d_in[2];
    const float* Wv   = (const float*)d_in[3];
    const float* Wo   = (const float*)d_in[4];
    const float* bo   = (const float*)d_in[5];
    const float* proj = (const float*)d_in[6];
    float* out = (float*)d_out;

    float *q, *k, *v, *qp, *kp, *kdg, *kmp, *km, *part, *ctx, *rq, *rk, *w;
    __nv_bfloat16 *wh, *wl, *xh, *xl, *ath, *atl;
    cudaGetSymbolAddress((void**)&q, g_q);
    cudaGetSymbolAddress((void**)&k, g_k);
    cudaGetSymbolAddress((void**)&v, g_v);
    cudaGetSymbolAddress((void**)&qp, g_qp);
    cudaGetSymbolAddress((void**)&kp, g_kp);
    cudaGetSymbolAddress((void**)&kdg, g_kdiag);
    cudaGetSymbolAddress((void**)&kmp, g_kmaxp);
    cudaGetSymbolAddress((void**)&km, g_kmax);
    cudaGetSymbolAddress((void**)&part, g_part);
    cudaGetSymbolAddress((void**)&ctx, g_ctx);
    cudaGetSymbolAddress((void**)&rq, g_rq);
    cudaGetSymbolAddress((void**)&rk, g_rk);
    cudaGetSymbolAddress((void**)&w, g_w);
    cudaGetSymbolAddress((void**)&wh, g_wh);
    cudaGetSymbolAddress((void**)&wl, g_wl);
    cudaGetSymbolAddress((void**)&xh, g_xh);
    cudaGetSymbolAddress((void**)&xl, g_xl);
    cudaGetSymbolAddress((void**)&ath, g_ath);
    cudaGetSymbolAddress((void**)&atl, g_atl);

    cudaFuncSetAttribute(gemm_bfq, cudaFuncAttributeMaxDynamicSharedMemorySize, GSMEM_BYTES);
    cudaFuncSetAttribute(flashlocal, cudaFuncAttributeMaxDynamicSharedMemorySize, FL_SMEM);

    const int M = BB * NN; // 16384

    // weights: transpose then convert; x: convert
    dim3 tb(32, 8), tg(16, 16, 4);
    wtrans4<<<tg, tb>>>(Wq, Wk, Wv, Wo, w);
    conv_hl<<<4 * 512 * 512 / 2048, 256>>>(w, wh, wl);
    conv_hl<<<(size_t)M * DIMM / 2048, 256>>>(x, xh, xl);

    // fused QKV projection (grid.x = 24 -> routes to q/k/v)
    gemm_bfq<<<dim3(24, M / 128), 256, GSMEM_BYTES>>>(xh, xl, wh, wl, nullptr, q, k, v);

    dim3 gdd(NN / 64, BHG);
    ddq_mma<<<gdd, 256>>>(q, proj, qp);
    ddk_mma<<<gdd, 256>>>(k, proj, kp, kdg, kmp);
    kmax_final_kernel<<<BHG, 128>>>(kmp, km);

    ctx_partial_kernel<<<dim3(BHG, NSPLIT), 256>>>(kp, kdg, km, v, part);
    ctx_reduce_kernel<<<(BHG * 256 * 65 + 255) / 256, 256>>>(part, ctx);

    outg_kernel<<<dim3(NN / 64, BHG), 256>>>(qp, ctx, ath, atl);

    rope_kernel<<<BHL * NN * 32 / 256, 256>>>(q, k, rq, rk);
    flashlocal<<<dim3(4, BHL * NWIN), 256, FL_SMEM>>>(rq, rk, v, ath, atl);

    // output projection (att already in bf16 hi/lo)
    gemm_bfq<<<dim3(8, M / 128), 256, GSMEM_BYTES>>>(ath, atl, wh + 3 * 512 * 512, wl + 3 * 512 * 512,
                                                     bo, out, out, out);
}

// round 17
// speedup vs baseline: 1.0601x; 1.0336x over previous
#include <cuda_runtime.h>
#include <cuda_bf16.h>
#include <math.h>
#include <stdint.h>

#define BB 2
#define NN 8192
#define DIMM 512
#define GH 6
#define DH 64
#define NBF 256
#define NWIN 32
#define WINSZ 256
#define BHG (BB*GH)      // 12
#define BHL 4            // B * LOCAL_HEADS
#define NSPLIT 32

// ---------------- scratch (device globals: alloc-free) ----------------
__device__ float g_q[BB*NN*DIMM];
__device__ float g_k[BB*NN*DIMM];
__device__ float g_v[BB*NN*DIMM];
__device__ float g_qp[BHG*NN*NBF];
__device__ float g_kp[BHG*NN*NBF];      // raw k dd scores
__device__ float g_kdiag[BHG*NN];
__device__ float g_kmaxp[BHG*128];
__device__ float g_kmax[BHG];
__device__ float g_part[BHG*NSPLIT*256*65];
__device__ float g_ctxT[BHG*68*256];    // transposed ctx: [bh][d][j], row 64 = k_sum
__device__ float g_rq[BHL*NN*DH];
__device__ float g_rk[BHL*NN*DH];
__device__ float g_w[4*512*512];
__device__ __nv_bfloat16 g_wh[4*512*512];
__device__ __nv_bfloat16 g_wl[4*512*512];
__device__ __nv_bfloat16 g_xh[BB*NN*DIMM];
__device__ __nv_bfloat16 g_xl[BB*NN*DIMM];
__device__ __nv_bfloat16 g_ath[BB*NN*DIMM];
__device__ __nv_bfloat16 g_atl[BB*NN*DIMM];

// ================= bf16 hi/lo split helpers =================
__device__ __forceinline__ void cvt_hl(float f0, float f1, uint32_t& hi, uint32_t& lo) {
    __nv_bfloat16 h0 = __float2bfloat16_rn(f0), h1 = __float2bfloat16_rn(f1);
    float r0 = f0 - __bfloat162float(h0), r1 = f1 - __bfloat162float(h1);
    __nv_bfloat162 hh; hh.x = h0; hh.y = h1;
    __nv_bfloat162 ll = __floats2bfloat162_rn(r0, r1);
    hi = *reinterpret_cast<uint32_t*>(&hh);
    lo = *reinterpret_cast<uint32_t*>(&ll);
}
__device__ __forceinline__ void mma_bf16(float* c, const uint32_t* a, const uint32_t* b) {
    asm volatile(
        "mma.sync.aligned.m16n8k16.row.col.f32.bf16.bf16.f32 "
        "{%0,%1,%2,%3}, {%4,%5,%6,%7}, {%8,%9}, {%0,%1,%2,%3};"
        : "+f"(c[0]), "+f"(c[1]), "+f"(c[2]), "+f"(c[3])
        : "r"(a[0]), "r"(a[1]), "r"(a[2]), "r"(a[3]), "r"(b[0]), "r"(b[1]));
}
__device__ __forceinline__ uint32_t cvta_smem(const void* p) {
    uint32_t a;
    asm("{ .reg .u64 t; cvta.to.shared.u64 t, %1; cvt.u32.u64 %0, t; }" : "=r"(a) : "l"(p));
    return a;
}
__device__ __forceinline__ void ldsm_x4(uint32_t addr, uint32_t* d) {
    asm volatile("ldmatrix.sync.aligned.m8n8.x4.shared.b16 {%0,%1,%2,%3}, [%4];"
        : "=r"(d[0]), "=r"(d[1]), "=r"(d[2]), "=r"(d[3]) : "r"(addr));
}
__device__ __forceinline__ void cp16(uint32_t s, const void* g) {
    asm volatile("cp.async.cg.shared.global [%0], [%1], 16;" :: "r"(s), "l"(g));
}
#define CP_COMMIT() asm volatile("cp.async.commit_group;" ::: "memory")
#define CP_WAIT1()  asm volatile("cp.async.wait_group 1;" ::: "memory")
#define CP_WAIT0()  asm volatile("cp.async.wait_group 0;" ::: "memory")

// ================= weight transpose (all 4 in one launch) =================
__global__ void wtrans4(const float* __restrict__ W0, const float* __restrict__ W1,
                        const float* __restrict__ W2, const float* __restrict__ W3,
                        float* __restrict__ wout)
{
    __shared__ float t[32][33];
    const float* W = (blockIdx.z == 0) ? W0 : (blockIdx.z == 1) ? W1 : (blockIdx.z == 2) ? W2 : W3;
    float* out = wout + (size_t)blockIdx.z * 512 * 512;
    int n0 = blockIdx.x * 32, k0 = blockIdx.y * 32;
    int tx = threadIdx.x, ty = threadIdx.y;
#pragma unroll
    for (int i = ty; i < 32; i += 8) t[i][tx] = W[(size_t)(k0 + i) * 512 + n0 + tx];
    __syncthreads();
#pragma unroll
    for (int i = ty; i < 32; i += 8) out[(size_t)(n0 + i) * 512 + k0 + tx] = t[tx][i];
}

// ================= fp32 -> bf16 hi/lo conversion (8 elems/thread) =================
__global__ void conv_hl(const float* __restrict__ in, __nv_bfloat16* __restrict__ oh,
                        __nv_bfloat16* __restrict__ ol)
{
    size_t i = ((size_t)blockIdx.x * 256 + threadIdx.x) * 8;
    float4 a = *(const float4*)(in + i), b = *(const float4*)(in + i + 4);
    float v[8] = {a.x, a.y, a.z, a.w, b.x, b.y, b.z, b.w};
    uint32_t h[4], l[4];
#pragma unroll
    for (int j = 0; j < 4; j++) cvt_hl(v[2*j], v[2*j+1], h[j], l[j]);
    *(uint4*)(oh + i) = make_uint4(h[0], h[1], h[2], h[3]);
    *(uint4*)(ol + i) = make_uint4(l[0], l[1], l[2], l[3]);
}

// ================= bf16x3 GEMM 128x64: cp.async 3-stage + ldmatrix + mma =================
#define STW 20
#define STAGE_W 7680
#define GSMEM_BYTES (3*STAGE_W*4)

__global__ void __launch_bounds__(256, 2) gemm_bfq(
    const __nv_bfloat16* __restrict__ Ah, const __nv_bfloat16* __restrict__ Al,
    const __nv_bfloat16* __restrict__ Bh, const __nv_bfloat16* __restrict__ Bl,
    const float* __restrict__ bias,
    float* __restrict__ o0, float* __restrict__ o1, float* __restrict__ o2)
{
    extern __shared__ uint32_t smw[];
    const int K = 512;
    const int NC = 16;
    int tid = threadIdx.x;
    int wid = tid >> 5, lane = tid & 31;
    int wm = wid >> 1, wn = wid & 1;
    int m0 = blockIdx.y * 128, n0 = blockIdx.x * 64;
    int r = lane >> 2, cq = lane & 3;
    int lr = lane & 7, lg = lane >> 3;
    float acc[2][4][4] = {};
    uint32_t smbase = cvta_smem(smw);
    uint32_t aoff = (uint32_t)(((wm * 32 + (lg & 1) * 8 + lr) * STW + (lg >> 1) * 4) * 4);
    uint32_t boff = (uint32_t)(((wn * 32 + (lg >> 1) * 8 + lr) * STW + (lg & 1) * 4) * 4);

    int arow = tid >> 1, acz = (tid & 1) * 16;
    int brow = tid >> 2, bcz = (tid & 3) * 8;
    const __nv_bfloat16* agh = Ah + (size_t)(m0 + arow) * K + acz;
    const __nv_bfloat16* agl = Al + (size_t)(m0 + arow) * K + acz;
    const __nv_bfloat16* bgh = Bh + (size_t)(n0 + brow) * K + bcz;
    const __nv_bfloat16* bgl = Bl + (size_t)(n0 + brow) * K + bcz;
    uint32_t as_off = (uint32_t)((arow * STW + (tid & 1) * 8) * 4);
    uint32_t bs_off = (uint32_t)((brow * STW + (tid & 3) * 4) * 4);

#define PREFETCH(s, k0) do { \
    uint32_t st = smbase + (uint32_t)(s) * (STAGE_W * 4); \
    cp16(st + as_off,                 agh + (k0)); \
    cp16(st + as_off + 16,            agh + (k0) + 8); \
    cp16(st + 2560 * 4 + as_off,      agl + (k0)); \
    cp16(st + 2560 * 4 + as_off + 16, agl + (k0) + 8); \
    cp16(st + 5120 * 4 + bs_off,      bgh + (k0)); \
    cp16(st + 6400 * 4 + bs_off,      bgl + (k0)); \
    CP_COMMIT(); \
} while (0)

#define DO_MMA(s) do { \
    uint32_t sb0 = smbase + (uint32_t)(s) * (STAGE_W * 4); \
    _Pragma("unroll") \
    for (int ks = 0; ks < 2; ks++) { \
        uint32_t kb = (uint32_t)(ks * 32); \
        uint32_t ah[2][4], al[2][4], bq[2][4], bl[2][4]; \
        _Pragma("unroll") \
        for (int mt = 0; mt < 2; mt++) { \
            ldsm_x4(sb0 + aoff + mt * (16 * STW * 4) + kb, ah[mt]); \
            ldsm_x4(sb0 + 2560 * 4 + aoff + mt * (16 * STW * 4) + kb, al[mt]); \
        } \
        _Pragma("unroll") \
        for (int p = 0; p < 2; p++) { \
            ldsm_x4(sb0 + 5120 * 4 + boff + p * (16 * STW * 4) + kb, bq[p]); \
            ldsm_x4(sb0 + 6400 * 4 + boff + p * (16 * STW * 4) + kb, bl[p]); \
        } \
        _Pragma("unroll") \
        for (int mt = 0; mt < 2; mt++) \
            _Pragma("unroll") \
            for (int nt = 0; nt < 4; nt++) { \
                const uint32_t* bh2 = &bq[nt >> 1][(nt & 1) * 2]; \
                const uint32_t* bl2 = &bl[nt >> 1][(nt & 1) * 2]; \
                mma_bf16(acc[mt][nt], ah[mt], bh2); \
                mma_bf16(acc[mt][nt], ah[mt], bl2); \
                mma_bf16(acc[mt][nt], al[mt], bh2); \
            } \
    } \
} while (0)

    PREFETCH(0, 0);
    PREFETCH(1, 32);
    for (int it = 0; it < NC; ++it) {
        if (it < NC - 1) { CP_WAIT1(); } else { CP_WAIT0(); }
        __syncthreads();
        if (it + 2 < NC) PREFETCH((it + 2) % 3, (it + 2) * 32);
        DO_MMA(it % 3);
    }

    int sel = n0 >> 9;
    int colb = n0 & 511;
    float* ob = (sel == 0) ? o0 : (sel == 1) ? o1 : o2;
#pragma unroll
    for (int mt = 0; mt < 2; mt++)
#pragma unroll
        for (int nt = 0; nt < 4; nt++) {
            int row = m0 + wm * 32 + mt * 16 + r;
            int col = colb + wn * 32 + nt * 8 + 2 * cq;
            float2 v0 = make_float2(acc[mt][nt][0], acc[mt][nt][1]);
            float2 v1 = make_float2(acc[mt][nt][2], acc[mt][nt][3]);
            if (bias) {
                float2 bv = *(const float2*)(bias + col);
                v0.x += bv.x; v0.y += bv.y;
                v1.x += bv.x; v1.y += bv.y;
            }
            *(float2*)(ob + (size_t)row * 512 + col) = v0;
            *(float2*)(ob + (size_t)(row + 8) * 512 + col) = v1;
        }
#undef PREFETCH
#undef DO_MMA
}

// ================= dd via bf16x3 mma: CTA = 64 rows x 256 features, K=64 =================
#define DSTW 12

#define DD_MAINLOOP() \
    float acc[2][8][4]; \
    _Pragma("unroll") \
    for (int i = 0; i < 2; i++) _Pragma("unroll") for (int j = 0; j < 8; j++) \
        _Pragma("unroll") for (int t = 0; t < 4; t++) acc[i][j][t] = 0.f; \
    int ar = tid >> 2, akq = (tid & 3) * 4; \
    const float* ab = data + ((size_t)b * NN + n0 + ar) * DIMM + h * 64 + akq; \
    const float* pbb = proj + (size_t)tid * 64; \
    float sumsq = 0.f; \
    for (int kc = 0; kc < 4; kc++) { \
        float4 va = *(const float4*)(ab + kc * 16); \
        float x0 = va.x * NORM, x1 = va.y * NORM, x2 = va.z * NORM, x3 = va.w * NORM; \
        sumsq += x0 * x0 + x1 * x1 + x2 * x2 + x3 * x3; \
        uint32_t ah0, al0, ah1, al1; \
        cvt_hl(x0, x1, ah0, al0); cvt_hl(x2, x3, ah1, al1); \
        float4 vb0 = *(const float4*)(pbb + kc * 16); \
        float4 vb1 = *(const float4*)(pbb + kc * 16 + 4); \
        float4 vb2 = *(const float4*)(pbb + kc * 16 + 8); \
        float4 vb3 = *(const float4*)(pbb + kc * 16 + 12); \
        float bvv[16] = {vb0.x,vb0.y,vb0.z,vb0.w, vb1.x,vb1.y,vb1.z,vb1.w, \
                         vb2.x,vb2.y,vb2.z,vb2.w, vb3.x,vb3.y,vb3.z,vb3.w}; \
        uint32_t bhv[8], blv[8]; \
        _Pragma("unroll") \
        for (int i = 0; i < 8; i++) cvt_hl(bvv[2*i], bvv[2*i+1], bhv[i], blv[i]); \
        __syncthreads(); \
        *(uint2*)(Ahs + ar * DSTW + (akq >> 1)) = make_uint2(ah0, ah1); \
        *(uint2*)(Als + ar * DSTW + (akq >> 1)) = make_uint2(al0, al1); \
        *(uint4*)(Bhs + tid * DSTW)     = make_uint4(bhv[0], bhv[1], bhv[2], bhv[3]); \
        *(uint4*)(Bhs + tid * DSTW + 4) = make_uint4(bhv[4], bhv[5], bhv[6], bhv[7]); \
        *(uint4*)(Bls + tid * DSTW)     = make_uint4(blv[0], blv[1], blv[2], blv[3]); \
        *(uint4*)(Bls + tid * DSTW + 4) = make_uint4(blv[4], blv[5], blv[6], blv[7]); \
        __syncthreads(); \
        uint32_t afh[2][4], afl[2][4]; \
        _Pragma("unroll") \
        for (int mt = 0; mt < 2; mt++) { \
            int mr = (wm * 32 + mt * 16 + r) * DSTW + cq; \
            afh[mt][0] = Ahs[mr];       afh[mt][1] = Ahs[mr + 8 * DSTW]; \
            afh[mt][2] = Ahs[mr + 4];   afh[mt][3] = Ahs[mr + 8 * DSTW + 4]; \
            afl[mt][0] = Als[mr];       afl[mt][1] = Als[mr + 8 * DSTW]; \
            afl[mt][2] = Als[mr + 4];   afl[mt][3] = Als[mr + 8 * DSTW + 4]; \
        } \
        _Pragma("unroll") \
        for (int nt = 0; nt < 8; nt++) { \
            int nr = (wn * 64 + nt * 8 + r) * DSTW + cq; \
            uint32_t bf[2] = {Bhs[nr], Bhs[nr + 4]}; \
            uint32_t bg[2] = {Bls[nr], Bls[nr + 4]}; \
            _Pragma("unroll") \
            for (int mt = 0; mt < 2; mt++) { \
                mma_bf16(acc[mt][nt], afh[mt], bf); \
                mma_bf16(acc[mt][nt], afh[mt], bg); \
                mma_bf16(acc[mt][nt], afl[mt], bf); \
            } \
        } \
    }

__global__ void __launch_bounds__(256, 2) ddq_mma(
    const float* __restrict__ data, const float* __restrict__ proj, float* __restrict__ qp)
{
    __shared__ uint32_t Ahs[64*DSTW], Als[64*DSTW], Bhs[256*DSTW], Bls[256*DSTW];
    __shared__ float ssq[64][4];
    __shared__ float wred[64][4];
    __shared__ float rowbase[64];
    int bh = blockIdx.y; int b = bh / GH, h = bh % GH;
    int n0 = blockIdx.x * 64;
    int tid = threadIdx.x;
    int wid = tid >> 5, lane = tid & 31;
    int wm = wid >> 2, wn = wid & 3;
    int r = lane >> 2, cq = lane & 3;
    const float NORM = 0.35355339059327373f;

    DD_MAINLOOP();

    ssq[ar][tid & 3] = sumsq;
    float mx[2][2];
#pragma unroll
    for (int mt = 0; mt < 2; mt++)
#pragma unroll
        for (int hf = 0; hf < 2; hf++) {
            float m = -1e30f;
#pragma unroll
            for (int nt = 0; nt < 8; nt++)
                m = fmaxf(m, fmaxf(acc[mt][nt][hf*2], acc[mt][nt][hf*2+1]));
            m = fmaxf(m, __shfl_xor_sync(0xffffffffu, m, 1));
            m = fmaxf(m, __shfl_xor_sync(0xffffffffu, m, 2));
            mx[mt][hf] = m;
        }
    if (cq == 0) {
#pragma unroll
        for (int mt = 0; mt < 2; mt++)
#pragma unroll
            for (int hf = 0; hf < 2; hf++)
                wred[wm * 32 + mt * 16 + hf * 8 + r][wn] = mx[mt][hf];
    }
    __syncthreads();
    if (tid < 64) {
        float mm = fmaxf(fmaxf(wred[tid][0], wred[tid][1]), fmaxf(wred[tid][2], wred[tid][3]));
        float dg = 0.5f * (ssq[tid][0] + ssq[tid][1] + ssq[tid][2] + ssq[tid][3]);
        rowbase[tid] = dg + mm;
    }
    __syncthreads();
#pragma unroll
    for (int mt = 0; mt < 2; mt++) {
        int row_a = wm * 32 + mt * 16 + r, row_b = row_a + 8;
        float ba = rowbase[row_a], bb2 = rowbase[row_b];
        float* oa = qp + ((size_t)bh * NN + n0 + row_a) * NBF;
        float* ob = qp + ((size_t)bh * NN + n0 + row_b) * NBF;
#pragma unroll
        for (int nt = 0; nt < 8; nt++) {
            int col = wn * 64 + nt * 8 + 2 * cq;
            float2 o1, o2;
            o1.x = 0.0625f * (expf(acc[mt][nt][0] - ba) + 1e-4f);
            o1.y = 0.0625f * (expf(acc[mt][nt][1] - ba) + 1e-4f);
            o2.x = 0.0625f * (expf(acc[mt][nt][2] - bb2) + 1e-4f);
            o2.y = 0.0625f * (expf(acc[mt][nt][3] - bb2) + 1e-4f);
            *(float2*)(oa + col) = o1;
            *(float2*)(ob + col) = o2;
        }
    }
}

__global__ void __launch_bounds__(256, 2) ddk_mma(
    const float* __restrict__ data, const float* __restrict__ proj,
    float* __restrict__ kdd, float* __restrict__ kdiag, float* __restrict__ kmaxp)
{
    __shared__ uint32_t Ahs[64*DSTW], Als[64*DSTW], Bhs[256*DSTW], Bls[256*DSTW];
    __shared__ float ssq[64][4];
    __shared__ float red[8];
    int bh = blockIdx.y; int b = bh / GH, h = bh % GH;
    int n0 = blockIdx.x * 64;
    int tid = threadIdx.x;
    int wid = tid >> 5, lane = tid & 31;
    int wm = wid >> 2, wn = wid & 3;
    int r = lane >> 2, cq = lane & 3;
    const float NORM = 0.35355339059327373f;

    DD_MAINLOOP();

    ssq[ar][tid & 3] = sumsq;
    __syncthreads();
    if (tid < 64)
        kdiag[(size_t)bh * NN + n0 + tid] =
            0.5f * (ssq[tid][0] + ssq[tid][1] + ssq[tid][2] + ssq[tid][3]);
    float tmax = -1e30f;
#pragma unroll
    for (int mt = 0; mt < 2; mt++) {
        int row_a = wm * 32 + mt * 16 + r, row_b = row_a + 8;
        float* oa = kdd + ((size_t)bh * NN + n0 + row_a) * NBF;
        float* ob = kdd + ((size_t)bh * NN + n0 + row_b) * NBF;
#pragma unroll
        for (int nt = 0; nt < 8; nt++) {
            int col = wn * 64 + nt * 8 + 2 * cq;
            float2 o1 = make_float2(acc[mt][nt][0], acc[mt][nt][1]);
            float2 o2 = make_float2(acc[mt][nt][2], acc[mt][nt][3]);
            tmax = fmaxf(tmax, fmaxf(fmaxf(o1.x, o1.y), fmaxf(o2.x, o2.y)));
            *(float2*)(oa + col) = o1;
            *(float2*)(ob + col) = o2;
        }
    }
#pragma unroll
    for (int o = 16; o > 0; o >>= 1) tmax = fmaxf(tmax, __shfl_xor_sync(0xffffffffu, tmax, o));
    if (lane == 0) red[wid] = tmax;
    __syncthreads();
    if (tid == 0) {
        float z = red[0];
#pragma unroll
        for (int i = 1; i < 8; i++) z = fmaxf(z, red[i]);
        kmaxp[bh * 128 + blockIdx.x] = z;
    }
}

__global__ void kmax_final_kernel(const float* __restrict__ kpart, float* __restrict__ kmax)
{
    int bh = blockIdx.x;
    float m = kpart[bh * 128 + threadIdx.x];
#pragma unroll
    for (int o = 16; o > 0; o >>= 1) m = fmaxf(m, __shfl_xor_sync(0xffffffffu, m, o));
    __shared__ float red[4];
    if ((threadIdx.x & 31) == 0) red[threadIdx.x >> 5] = m;
    __syncthreads();
    if (threadIdx.x == 0)
        kmax[bh] = fmaxf(fmaxf(red[0], red[1]), fmaxf(red[2], red[3]));
}

// ---------------- ctx: exp applied inline on raw kdd ----------------
__global__ void __launch_bounds__(256) ctx_partial_kernel(
    const float* __restrict__ kdd, const float* __restrict__ kdiag,
    const float* __restrict__ kmax, const float* __restrict__ v, float* __restrict__ part)
{
    int bh = blockIdx.x, sp = blockIdx.y;
    int b = bh / GH, h = bh % GH;
    int j = threadIdx.x;
    float acc[65];
#pragma unroll
    for (int d = 0; d < 65; d++) acc[d] = 0.f;
    __shared__ __align__(16) float vs[16][68];
    float km = kmax[bh];
    const float* kpb = kdd + ((size_t)bh * NN + sp * 256) * NBF + j;
    const float* dgb = kdiag + (size_t)bh * NN + sp * 256;
    const float* vb = v + ((size_t)b * NN + sp * 256) * DIMM + h * 64;
    for (int n0 = 0; n0 < 256; n0 += 16) {
        __syncthreads();
        int r = threadIdx.x >> 4;
        int c = (threadIdx.x & 15) * 4;
        float4 vv = *(const float4*)(vb + (size_t)(n0 + r) * DIMM + c);
        *(float4*)&vs[r][c] = vv;
        if ((threadIdx.x & 15) == 0) vs[r][64] = 1.f;
        if ((threadIdx.x & 15) == 1) vs[r][65] = dgb[n0 + r];
        __syncthreads();
#pragma unroll 2
        for (int nn = 0; nn < 16; nn++) {
            float praw = kpb[(size_t)(n0 + nn) * NBF];
            float p = 0.0625f * (expf(praw - vs[nn][65] - km) + 1e-4f);
#pragma unroll
            for (int d = 0; d < 65; d++) acc[d] += p * vs[nn][d];
        }
    }
    float* o = part + (((size_t)bh * NSPLIT + sp) * 256 + j) * 65;
#pragma unroll
    for (int d = 0; d < 65; d++) o[d] = acc[d];
}
// reduce -> transposed ctxT[bh][d][j]
__global__ void ctx_reduce_kernel(const float* __restrict__ part, float* __restrict__ ctxT)
{
    int idx = blockIdx.x * 256 + threadIdx.x;
    if (idx >= BHG * 256 * 65) return;
    int bh = idx / (256 * 65); int rem = idx - bh * 256 * 65;
    int j = rem / 65, d = rem % 65;
    float s = 0.f;
#pragma unroll
    for (int sp = 0; sp < NSPLIT; sp++)
        s += part[(((size_t)bh * NSPLIT + sp) * 256 + j) * 65 + d];
    ctxT[((size_t)bh * 68 + d) * 256 + j] = s;
}

// ======= out_g via bf16x3 mma: CTA = 64 n-rows x 64 d-cols, K = 256 (dsum fused) =======
#define OSTW 20
__global__ void __launch_bounds__(256, 2) outg_mma(
    const float* __restrict__ qp, const float* __restrict__ ctxT,
    __nv_bfloat16* __restrict__ ath, __nv_bfloat16* __restrict__ atl)
{
    __shared__ uint32_t Ah[64*OSTW], Al[64*OSTW], Bh[64*OSTW], Bl[64*OSTW];
    __shared__ float dsp[64][4];
    int bh = blockIdx.y; int b = bh / GH, h = bh % GH;
    int n0 = blockIdx.x * 64;
    int tid = threadIdx.x;
    int wid = tid >> 5, lane = tid & 31;
    int wm = wid >> 2, wn = wid & 3;   // 2(m) x 4(n): warp tile 32 rows x 16 cols
    int r = lane >> 2, cq = lane & 3;
    float acc[2][2][4] = {};
    int arow = tid >> 2, akq = (tid & 3) * 8;
    const float* qbase = qp + ((size_t)bh * NN + n0 + arow) * NBF + akq;
    const float* cbase = ctxT + ((size_t)bh * 68 + arow) * 256 + akq;   // row arow = d
    const float* ksg = ctxT + ((size_t)bh * 68 + 64) * 256 + akq;      // ksum row
    float dsum_acc = 0.f;

    for (int k0 = 0; k0 < 256; k0 += 32) {
        float4 a0 = *(const float4*)(qbase + k0);
        float4 a1 = *(const float4*)(qbase + k0 + 4);
        float av[8] = {a0.x,a0.y,a0.z,a0.w,a1.x,a1.y,a1.z,a1.w};
        float4 b0 = *(const float4*)(cbase + k0);
        float4 b1 = *(const float4*)(cbase + k0 + 4);
        float bv[8] = {b0.x,b0.y,b0.z,b0.w,b1.x,b1.y,b1.z,b1.w};
        uint32_t ahv[4], alv[4], bhv[4], blv[4];
#pragma unroll
        for (int i = 0; i < 4; i++) {
            cvt_hl(av[2*i], av[2*i+1], ahv[i], alv[i]);
            cvt_hl(bv[2*i], bv[2*i+1], bhv[i], blv[i]);
        }
        float4 ks0 = *(const float4*)(ksg + k0);
        float4 ks1 = *(const float4*)(ksg + k0 + 4);
        dsum_acc += av[0]*ks0.x + av[1]*ks0.y + av[2]*ks0.z + av[3]*ks0.w
                  + av[4]*ks1.x + av[5]*ks1.y + av[6]*ks1.z + av[7]*ks1.w;
        __syncthreads();
        int soff = arow * OSTW + (akq >> 1);
        *(uint4*)(Ah + soff) = make_uint4(ahv[0], ahv[1], ahv[2], ahv[3]);
        *(uint4*)(Al + soff) = make_uint4(alv[0], alv[1], alv[2], alv[3]);
        *(uint4*)(Bh + soff) = make_uint4(bhv[0], bhv[1], bhv[2], bhv[3]);
        *(uint4*)(Bl + soff) = make_uint4(blv[0], blv[1], blv[2], blv[3]);
        __syncthreads();
#pragma unroll
        for (int ks = 0; ks < 2; ks++) {
            int ko = ks * 8;
            uint32_t afh[2][4], afl[2][4];
#pragma unroll
            for (int mt = 0; mt < 2; mt++) {
                int mr = (wm * 32 + mt * 16 + r) * OSTW + ko + cq;
                afh[mt][0] = Ah[mr];       afh[mt][1] = Ah[mr + 8 * OSTW];
                afh[mt][2] = Ah[mr + 4];   afh[mt][3] = Ah[mr + 8 * OSTW + 4];
                afl[mt][0] = Al[mr];       afl[mt][1] = Al[mr + 8 * OSTW];
                afl[mt][2] = Al[mr + 4];   afl[mt][3] = Al[mr + 8 * OSTW + 4];
            }
#pragma unroll
            for (int nt = 0; nt < 2; nt++) {
                int nr = (wn * 16 + nt * 8 + r) * OSTW + ko + cq;
                uint32_t bf[2] = {Bh[nr], Bh[nr + 4]};
                uint32_t bg[2] = {Bl[nr], Bl[nr + 4]};
#pragma unroll
                for (int mt = 0; mt < 2; mt++) {
                    mma_bf16(acc[mt][nt], afh[mt], bf);
                    mma_bf16(acc[mt][nt], afh[mt], bg);
                    mma_bf16(acc[mt][nt], afl[mt], bf);
                }
            }
        }
    }
    dsp[arow][tid & 3] = dsum_acc;
    __syncthreads();
#pragma unroll
    for (int mt = 0; mt < 2; mt++) {
        int rowA = wm * 32 + mt * 16 + r, rowB = rowA + 8;
        float dA = 1.f / (dsp[rowA][0] + dsp[rowA][1] + dsp[rowA][2] + dsp[rowA][3]);
        float dB = 1.f / (dsp[rowB][0] + dsp[rowB][1] + dsp[rowB][2] + dsp[rowB][3]);
#pragma unroll
        for (int nt = 0; nt < 2; nt++) {
            int col = wn * 16 + nt * 8 + 2 * cq;
            uint32_t hA, lA, hB, lB;
            cvt_hl(acc[mt][nt][0] * dA, acc[mt][nt][1] * dA, hA, lA);
            cvt_hl(acc[mt][nt][2] * dB, acc[mt][nt][3] * dB, hB, lB);
            size_t offA = ((size_t)b * NN + n0 + rowA) * DIMM + h * 64 + col;
            size_t offB = ((size_t)b * NN + n0 + rowB) * DIMM + h * 64 + col;
            *(uint32_t*)(ath + offA) = hA;
            *(uint32_t*)(atl + offA) = lA;
            *(uint32_t*)(ath + offB) = hB;
            *(uint32_t*)(atl + offB) = lB;
        }
    }
}

// ---------------- RoPE for local heads ----------------
__global__ void rope_kernel(const float* __restrict__ q, const float* __restrict__ k,
                            float* __restrict__ rq, float* __restrict__ rk)
{
    int idx = blockIdx.x * blockDim.x + threadIdx.x;
    int i = idx & 31;
    int n = (idx >> 5) & (NN - 1);
    int bh = idx >> 18;
    int b = bh >> 1, lh = bh & 1;
    float invf = (float)exp(-(double)(2 * i) / 64.0 * 9.210340371976184);
    float ang = (float)n * invf;
    float s, c;
    sincosf(ang, &s, &c);
    size_t base = ((size_t)b * NN + n) * DIMM + (GH + lh) * 64;
    float q1 = q[base + i], q2 = q[base + 32 + i];
    float k1 = k[base + i], k2 = k[base + 32 + i];
    size_t ob = ((size_t)bh * NN + n) * DH;
    rq[ob + i]      = q1 * c - q2 * s;
    rq[ob + 32 + i] = q2 * c + q1 * s;
    rk[ob + i]      = k1 * c - k2 * s;
    rk[ob + 32 + i] = k2 * c + k1 * s;
}

// ======== fused local attention: flash-style, 64 q-rows per CTA ========
#define FL_Q 0
#define FL_KP (64*68)
#define FL_V (2*64*68)
#define FL_RM (3*64*68)
#define FL_RS (3*64*68 + 64)
#define FL_SMEM ((3*64*68 + 128) * 4)

__global__ void __launch_bounds__(256) flashlocal(
    const float* __restrict__ rq, const float* __restrict__ rk,
    const float* __restrict__ v,
    __nv_bfloat16* __restrict__ ath, __nv_bfloat16* __restrict__ atl)
{
    extern __shared__ float sm[];
    float* Qs = sm + FL_Q;
    float* KP = sm + FL_KP;
    float* Vs = sm + FL_V;
    float* rowm = sm + FL_RM;
    float* rowsum = sm + FL_RS;
    int bw = blockIdx.y; int bh = bw >> 5; int w = bw & 31;
    int b = bh >> 1, lh = bh & 1;
    int m0 = blockIdx.x * 64;
    int tid = threadIdx.x;
    int tx = tid & 15, ty = tid >> 4;
    int lr = tid >> 2, lc4 = (tid & 3) * 4;

    const float* qb = rq + ((size_t)bh * NN + w * WINSZ + m0) * DH;
#pragma unroll
    for (int i = 0; i < 4; i++) {
        int c = lc4 + i * 16;
        float4 va = *(const float4*)(qb + (size_t)lr * DH + c);
        Qs[(c+0)*68 + lr] = va.x; Qs[(c+1)*68 + lr] = va.y;
        Qs[(c+2)*68 + lr] = va.z; Qs[(c+3)*68 + lr] = va.w;
    }
    if (tid < 64) { rowm[tid] = -1e30f; rowsum[tid] = 0.f; }
    float out[4][4] = {};
    __syncthreads();

    for (int c0 = 0; c0 < 768; c0 += 64) {
        int kn0 = (w - 1) * WINSZ + c0;
        if (kn0 < 0 || kn0 >= NN) continue;
        const float* kb = rk + ((size_t)bh * NN + kn0) * DH;
        const float* vb = v + ((size_t)b * NN + kn0) * DIMM + (GH + lh) * 64;
#pragma unroll
        for (int i = 0; i < 4; i++) {
            int c = lc4 + i * 16;
            float4 vk = *(const float4*)(kb + (size_t)lr * DH + c);
            KP[(c+0)*68 + lr] = vk.x; KP[(c+1)*68 + lr] = vk.y;
            KP[(c+2)*68 + lr] = vk.z; KP[(c+3)*68 + lr] = vk.w;
            float4 vv = *(const float4*)(vb + (size_t)lr * DIMM + c);
            *(float4*)&Vs[lr*68 + c] = vv;
        }
        __syncthreads();
        float s4[4][4] = {};
#pragma unroll
        for (int kk = 0; kk < 64; kk++) {
            float4 a  = *(const float4*)&Qs[kk*68 + ty*4];
            float4 bq = *(const float4*)&KP[kk*68 + tx*4];
            float av[4] = {a.x,a.y,a.z,a.w}, bb[4] = {bq.x,bq.y,bq.z,bq.w};
#pragma unroll
            for (int i = 0; i < 4; i++)
#pragma unroll
                for (int j = 0; j < 4; j++) s4[i][j] += av[i] * bb[j];
        }
        float f_i[4], mnew_i[4], rsum_i[4], p[4][4];
#pragma unroll
        for (int i = 0; i < 4; i++) {
            float mc = -1e30f;
#pragma unroll
            for (int j = 0; j < 4; j++) { s4[i][j] *= 0.125f; mc = fmaxf(mc, s4[i][j]); }
#pragma unroll
            for (int o = 8; o > 0; o >>= 1) mc = fmaxf(mc, __shfl_xor_sync(0xffffffffu, mc, o));
            float mold = rowm[ty*4 + i];
            float mnew = fmaxf(mold, mc);
            mnew_i[i] = mnew;
            f_i[i] = expf(mold - mnew);
            float rs = 0.f;
#pragma unroll
            for (int j = 0; j < 4; j++) { p[i][j] = expf(s4[i][j] - mnew); rs += p[i][j]; }
#pragma unroll
            for (int o = 8; o > 0; o >>= 1) rs += __shfl_xor_sync(0xffffffffu, rs, o);
            rsum_i[i] = rs;
        }
        __syncthreads();
        if (tx == 0) {
#pragma unroll
            for (int i = 0; i < 4; i++) {
                int row = ty*4 + i;
                rowm[row] = mnew_i[i];
                rowsum[row] = rowsum[row] * f_i[i] + rsum_i[i];
            }
        }
#pragma unroll
        for (int i = 0; i < 4; i++) {
            float4 pv = {p[i][0], p[i][1], p[i][2], p[i][3]};
            *(float4*)&KP[(ty*4 + i)*68 + tx*4] = pv;
#pragma unroll
            for (int j = 0; j < 4; j++) out[i][j] *= f_i[i];
        }
        __syncthreads();
#pragma unroll
        for (int kk = 0; kk < 64; kk++) {
            float4 bv = *(const float4*)&Vs[kk*68 + tx*4];
            float bb[4] = {bv.x, bv.y, bv.z, bv.w};
#pragma unroll
            for (int i = 0; i < 4; i++) {
                float a = KP[(ty*4 + i)*68 + kk];
#pragma unroll
                for (int j = 0; j < 4; j++) out[i][j] += a * bb[j];
            }
        }
        __syncthreads();
    }
#pragma unroll
    for (int i = 0; i < 4; i++) {
        int n = w * WINSZ + m0 + ty * 4 + i;
        float inv = 1.f / rowsum[ty*4 + i];
        float v0 = out[i][0]*inv, v1 = out[i][1]*inv, v2 = out[i][2]*inv, v3 = out[i][3]*inv;
        uint32_t h0, l0, h1, l1;
        cvt_hl(v0, v1, h0, l0);
        cvt_hl(v2, v3, h1, l1);
        size_t off = ((size_t)b * NN + n) * DIMM + (GH + lh) * 64 + tx * 4;
        *(uint2*)(ath + off) = make_uint2(h0, h1);
        *(uint2*)(atl + off) = make_uint2(l0, l1);
    }
}

// ---------------- launcher ----------------
extern "C" void kernel_launch(void* const* d_in, const int* in_sizes, int n_in,
                              void* d_out, int out_size)
{
    (void)in_sizes; (void)n_in; (void)out_size;
    const float* x    = (const float*)d_in[0];
    const float* Wq   = (const float*)d_in[1];
    const float* Wk   = (const float*)d_in[2];
    const float* Wv   = (const float*)d_in[3];
    const float* Wo   = (const float*)d_in[4];
    const float* bo   = (const float*)d_in[5];
    const float* proj = (const float*)d_in[6];
    float* out = (float*)d_out;

    float *q, *k, *v, *qp, *kp, *kdg, *kmp, *km, *part, *ctxT, *rq, *rk, *w;
    __nv_bfloat16 *wh, *wl, *xh, *xl, *ath, *atl;
    cudaGetSymbolAddress((void**)&q, g_q);
    cudaGetSymbolAddress((void**)&k, g_k);
    cudaGetSymbolAddress((void**)&v, g_v);
    cudaGetSymbolAddress((void**)&qp, g_qp);
    cudaGetSymbolAddress((void**)&kp, g_kp);
    cudaGetSymbolAddress((void**)&kdg, g_kdiag);
    cudaGetSymbolAddress((void**)&kmp, g_kmaxp);
    cudaGetSymbolAddress((void**)&km, g_kmax);
    cudaGetSymbolAddress((void**)&part, g_part);
    cudaGetSymbolAddress((void**)&ctxT, g_ctxT);
    cudaGetSymbolAddress((void**)&rq, g_rq);
    cudaGetSymbolAddress((void**)&rk, g_rk);
    cudaGetSymbolAddress((void**)&w, g_w);
    cudaGetSymbolAddress((void**)&wh, g_wh);
    cudaGetSymbolAddress((void**)&wl, g_wl);
    cudaGetSymbolAddress((void**)&xh, g_xh);
    cudaGetSymbolAddress((void**)&xl, g_xl);
    cudaGetSymbolAddress((void**)&ath, g_ath);
    cudaGetSymbolAddress((void**)&atl, g_atl);

    cudaFuncSetAttribute(gemm_bfq, cudaFuncAttributeMaxDynamicSharedMemorySize, GSMEM_BYTES);
    cudaFuncSetAttribute(flashlocal, cudaFuncAttributeMaxDynamicSharedMemorySize, FL_SMEM);

    const int M = BB * NN; // 16384

    dim3 tb(32, 8), tg(16, 16, 4);
    wtrans4<<<tg, tb>>>(Wq, Wk, Wv, Wo, w);
    conv_hl<<<4 * 512 * 512 / 2048, 256>>>(w, wh, wl);
    conv_hl<<<(size_t)M * DIMM / 2048, 256>>>(x, xh, xl);

    gemm_bfq<<<dim3(24, M / 128), 256, GSMEM_BYTES>>>(xh, xl, wh, wl, nullptr, q, k, v);

    dim3 gdd(NN / 64, BHG);
    ddq_mma<<<gdd, 256>>>(q, proj, qp);
    ddk_mma<<<gdd, 256>>>(k, proj, kp, kdg, kmp);
    kmax_final_kernel<<<BHG, 128>>>(kmp, km);

    ctx_partial_kernel<<<dim3(BHG, NSPLIT), 256>>>(kp, kdg, km, v, part);
    ctx_reduce_kernel<<<(BHG * 256 * 65 + 255) / 256, 256>>>(part, ctxT);

    outg_mma<<<dim3(NN / 64, BHG), 256>>>(qp, ctxT, ath, atl);

    rope_kernel<<<BHL * NN * 32 / 256, 256>>>(q, k, rq, rk);
    flashlocal<<<dim3(4, BHL * NWIN), 256, FL_SMEM>>>(rq, rk, v, ath, atl);

    gemm_bfq<<<dim3(8, M / 128), 256, GSMEM_BYTES>>>(ath, atl, wh + 3 * 512 * 512, wl + 3 * 512 * 512,
                                                     bo, out, out, out);
}